// round 1
// baseline (speedup 1.0000x reference)
#include <cuda_runtime.h>
#include <cuda_bf16.h>
#include <cstdint>

// Problem constants
#define NNODES 50000
#define NEDGES 800000
#define HID    128

// ---------------- scratch (device globals; no allocation allowed) ----------
__device__ float g_x[NNODES * HID];
__device__ float g_A[NNODES * HID];   // x @ W1a + b1   (later reused as update-hidden)
__device__ float g_B[NNODES * HID];   // x @ W1b        (later reused as x_new)
__device__ float g_S[NNODES * HID];   // edge scatter accumulator
__device__ float g_T[NNODES * HID];   // aggr
__device__ float g_deg[NNODES];
__device__ float g_inv[NNODES];
__device__ float g_mask[NNODES];
__device__ float g_colsum[HID];
__device__ int   g_is64;

// ---------------- index dtype detection ------------------------------------
__global__ void detect_idx_kernel(const void* idx, int E, int* flag) {
    const long long* p = (const long long*)idx;
    int is64 = 1;
    int n = (E < 128) ? E : 128;
    for (int i = 0; i < n; ++i) {
        long long v = p[i];
        if (v < 0 || v >= NNODES) { is64 = 0; break; }
    }
    *flag = is64;
}

__device__ __forceinline__ int load_idx(const void* idx, int is64, long long pos) {
    if (is64) return (int)((const long long*)idx)[pos];
    return ((const int*)idx)[pos];
}

// ---------------- degree ----------------------------------------------------
__global__ void deg_kernel(const void* __restrict__ idx, const int* __restrict__ flag,
                           float* __restrict__ deg, int E) {
    int e = blockIdx.x * blockDim.x + threadIdx.x;
    if (e >= E) return;
    int dst = load_idx(idx, *flag, (long long)E + e);
    atomicAdd(&deg[dst], 1.0f);
}

__global__ void invdeg_kernel(const float* __restrict__ deg, float* __restrict__ inv,
                              float* __restrict__ mask, int N) {
    int i = blockIdx.x * blockDim.x + threadIdx.x;
    if (i >= N) return;
    float d = deg[i];
    inv[i]  = 1.0f / fmaxf(d, 1.0f);
    mask[i] = (d > 0.0f) ? 1.0f : 0.0f;
}

// ---------------- encoder: x = node_feat @ enc_W + enc_b (K=5) --------------
__global__ void encoder_kernel(const float* __restrict__ nf, const float* __restrict__ W,
                               const float* __restrict__ b, float* __restrict__ x, int N) {
    int i = blockIdx.x * blockDim.x + threadIdx.x;
    if (i >= N * HID) return;
    int n = i >> 7;
    int h = i & 127;
    float acc = b[h];
#pragma unroll
    for (int k = 0; k < 5; ++k)
        acc = fmaf(nf[n * 5 + k], W[k * HID + h], acc);
    x[i] = acc;
}

// ---------------- generic 128-wide SGEMM ------------------------------------
// C[M,128] = f( A0[M,128]@W0[128,128] (+ A1@W1b) * (rowscale on A rows) + bias*biasmask )
__global__ __launch_bounds__(256) void sgemm128(
    const float* __restrict__ A0, const float* __restrict__ W0,
    const float* __restrict__ A1, const float* __restrict__ W1b,
    const float* __restrict__ bias,
    const float* __restrict__ rowscale,
    const float* __restrict__ biasmask,
    float* __restrict__ C, int M, int doRelu)
{
    __shared__ float As[8][132];
    __shared__ float Ws[8][128];
    const int tid = threadIdx.x;
    const int m0  = blockIdx.x * 128;
    const int ty  = tid >> 4;      // 0..15
    const int tx  = tid & 15;      // 0..15

    float acc[8][8];
#pragma unroll
    for (int i = 0; i < 8; ++i)
#pragma unroll
        for (int j = 0; j < 8; ++j) acc[i][j] = 0.0f;

    const int lr = tid >> 1;          // A-tile row 0..127
    const int lc = (tid & 1) * 4;     // A-tile col 0 or 4
    const int wr = tid >> 5;          // W-tile row 0..7
    const int wc = (tid & 31) * 4;    // W-tile col

    const int arow = m0 + lr;
    float rs = 1.0f;
    if (rowscale != nullptr && arow < M) rs = rowscale[arow];

    const int nops = (A1 != nullptr) ? 2 : 1;
    for (int op = 0; op < nops; ++op) {
        const float* A = op ? A1 : A0;
        const float* W = op ? W1b : W0;
        for (int k0 = 0; k0 < 128; k0 += 8) {
            __syncthreads();
            float4 av = make_float4(0.f, 0.f, 0.f, 0.f);
            if (arow < M)
                av = *reinterpret_cast<const float4*>(A + (size_t)arow * HID + k0 + lc);
            av.x *= rs; av.y *= rs; av.z *= rs; av.w *= rs;
            As[lc + 0][lr] = av.x;
            As[lc + 1][lr] = av.y;
            As[lc + 2][lr] = av.z;
            As[lc + 3][lr] = av.w;
            float4 wv = *reinterpret_cast<const float4*>(W + (size_t)(k0 + wr) * HID + wc);
            *reinterpret_cast<float4*>(&Ws[wr][wc]) = wv;
            __syncthreads();
#pragma unroll
            for (int k = 0; k < 8; ++k) {
                float a[8], b[8];
#pragma unroll
                for (int i = 0; i < 8; ++i) a[i] = As[k][ty * 8 + i];
#pragma unroll
                for (int j = 0; j < 8; ++j) b[j] = Ws[k][tx * 8 + j];
#pragma unroll
                for (int i = 0; i < 8; ++i)
#pragma unroll
                    for (int j = 0; j < 8; ++j)
                        acc[i][j] = fmaf(a[i], b[j], acc[i][j]);
            }
        }
    }

    // epilogue
#pragma unroll
    for (int i = 0; i < 8; ++i) {
        int r = m0 + ty * 8 + i;
        if (r >= M) continue;
        float bm = 1.0f;
        if (biasmask != nullptr) bm = biasmask[r];
        float out[8];
#pragma unroll
        for (int j = 0; j < 8; ++j) {
            float v = acc[i][j];
            if (bias != nullptr) v = fmaf(bm, bias[tx * 8 + j], v);
            if (doRelu) v = fmaxf(v, 0.0f);
            out[j] = v;
        }
        *reinterpret_cast<float4*>(C + (size_t)r * HID + tx * 8) =
            make_float4(out[0], out[1], out[2], out[3]);
        *reinterpret_cast<float4*>(C + (size_t)r * HID + tx * 8 + 4) =
            make_float4(out[4], out[5], out[6], out[7]);
    }
}

// ---------------- edge kernel: S[dst] += relu(A[dst] + B[src] + e*c) --------
__global__ __launch_bounds__(256) void edge_kernel(
    const float* __restrict__ A, const float* __restrict__ B,
    const float* __restrict__ eattr, const float* __restrict__ cvec,
    const void* __restrict__ eidx, const int* __restrict__ flag,
    float* __restrict__ S, int E)
{
    int e = (blockIdx.x << 3) + (threadIdx.x >> 5);
    if (e >= E) return;
    int lane = threadIdx.x & 31;
    int is64 = *flag;
    int src = load_idx(eidx, is64, e);
    int dst = load_idx(eidx, is64, (long long)E + e);
    float ea = eattr[e];
    const float4 a = *reinterpret_cast<const float4*>(A + (size_t)dst * HID + lane * 4);
    const float4 b = *reinterpret_cast<const float4*>(B + (size_t)src * HID + lane * 4);
    const float4 c = *reinterpret_cast<const float4*>(cvec + lane * 4);
    float4 v;
    v.x = fmaxf(fmaf(ea, c.x, a.x + b.x), 0.0f);
    v.y = fmaxf(fmaf(ea, c.y, a.y + b.y), 0.0f);
    v.z = fmaxf(fmaf(ea, c.z, a.z + b.z), 0.0f);
    v.w = fmaxf(fmaf(ea, c.w, a.w + b.w), 0.0f);
    float* sp = S + (size_t)dst * HID + lane * 4;
    atomicAdd(sp + 0, v.x);
    atomicAdd(sp + 1, v.y);
    atomicAdd(sp + 2, v.z);
    atomicAdd(sp + 3, v.w);
}

// ---------------- LayerNorm + ReLU (one warp per node) ----------------------
__global__ __launch_bounds__(256) void ln_relu_kernel(
    const float* __restrict__ in, const float* __restrict__ g,
    const float* __restrict__ b, float* __restrict__ out, int N)
{
    int node = (blockIdx.x * blockDim.x + threadIdx.x) >> 5;
    if (node >= N) return;
    int lane = threadIdx.x & 31;
    float4 v = *reinterpret_cast<const float4*>(in + (size_t)node * HID + lane * 4);
    float s = v.x + v.y + v.z + v.w;
#pragma unroll
    for (int o = 16; o > 0; o >>= 1) s += __shfl_xor_sync(0xffffffffu, s, o);
    float mu = s * (1.0f / 128.0f);
    float dx = v.x - mu, dy = v.y - mu, dz = v.z - mu, dw = v.w - mu;
    float q = dx * dx + dy * dy + dz * dz + dw * dw;
#pragma unroll
    for (int o = 16; o > 0; o >>= 1) q += __shfl_xor_sync(0xffffffffu, q, o);
    float rsd = rsqrtf(q * (1.0f / 128.0f) + 1e-5f);
    float4 gg = *reinterpret_cast<const float4*>(g + lane * 4);
    float4 bb = *reinterpret_cast<const float4*>(b + lane * 4);
    float4 r;
    r.x = fmaxf(fmaf(dx * rsd, gg.x, bb.x), 0.0f);
    r.y = fmaxf(fmaf(dy * rsd, gg.y, bb.y), 0.0f);
    r.z = fmaxf(fmaf(dz * rsd, gg.z, bb.z), 0.0f);
    r.w = fmaxf(fmaf(dw * rsd, gg.w, bb.w), 0.0f);
    *reinterpret_cast<float4*>(out + (size_t)node * HID + lane * 4) = r;
}

// ---------------- column sum (for final mean over nodes) --------------------
__global__ void colsum_kernel(const float* __restrict__ x, float* __restrict__ cs, int N) {
    int col = threadIdx.x & 127;
    int rg  = threadIdx.x >> 7;   // 0 or 1
    float s = 0.0f;
    for (int row = blockIdx.x * 2 + rg; row < N; row += gridDim.x * 2)
        s += x[(size_t)row * HID + col];
    atomicAdd(&cs[col], s);
}

// ---------------- output head: relu(g@W1+b1)@W2+b2 --------------------------
__global__ void head_kernel(const float* __restrict__ cs,
                            const float* __restrict__ W1, const float* __restrict__ b1,
                            const float* __restrict__ W2, const float* __restrict__ b2,
                            float* __restrict__ out, float invN)
{
    __shared__ float g[HID], h[HID];
    int t = threadIdx.x;
    g[t] = cs[t] * invN;
    __syncthreads();
    float acc = b1[t];
#pragma unroll 8
    for (int k = 0; k < HID; ++k) acc = fmaf(g[k], W1[k * HID + t], acc);
    h[t] = fmaxf(acc, 0.0f);
    __syncthreads();
    float o = b2[t];
#pragma unroll 8
    for (int k = 0; k < HID; ++k) o = fmaf(h[k], W2[k * HID + t], o);
    out[t] = o;
}

// ---------------- launch ----------------------------------------------------
extern "C" void kernel_launch(void* const* d_in, const int* in_sizes, int n_in,
                              void* d_out, int out_size) {
    const float* node_feat = (const float*)d_in[0];
    const float* edge_attr = (const float*)d_in[1];
    const float* enc_W     = (const float*)d_in[2];
    const float* enc_b     = (const float*)d_in[3];
    const float* mlp_W1    = (const float*)d_in[4];
    const float* mlp_b1    = (const float*)d_in[5];
    const float* mlp_W2    = (const float*)d_in[6];
    const float* mlp_b2    = (const float*)d_in[7];
    const float* upd_W1    = (const float*)d_in[8];
    const float* upd_b1    = (const float*)d_in[9];
    const float* upd_W2    = (const float*)d_in[10];
    const float* upd_b2    = (const float*)d_in[11];
    const float* ln_g      = (const float*)d_in[12];
    const float* ln_b      = (const float*)d_in[13];
    const float* out_W1    = (const float*)d_in[14];
    const float* out_b1    = (const float*)d_in[15];
    const float* out_W2    = (const float*)d_in[16];
    const float* out_b2    = (const float*)d_in[17];
    const void*  edge_idx  = d_in[18];

    const int N = in_sizes[0] / 5;
    const int E = in_sizes[18] / 2;

    float *px, *pA, *pB, *pS, *pT, *pdeg, *pinv, *pmask, *pcs;
    int* pflag;
    cudaGetSymbolAddress((void**)&px,    g_x);
    cudaGetSymbolAddress((void**)&pA,    g_A);
    cudaGetSymbolAddress((void**)&pB,    g_B);
    cudaGetSymbolAddress((void**)&pS,    g_S);
    cudaGetSymbolAddress((void**)&pT,    g_T);
    cudaGetSymbolAddress((void**)&pdeg,  g_deg);
    cudaGetSymbolAddress((void**)&pinv,  g_inv);
    cudaGetSymbolAddress((void**)&pmask, g_mask);
    cudaGetSymbolAddress((void**)&pcs,   g_colsum);
    cudaGetSymbolAddress((void**)&pflag, g_is64);

    const int gemm_grid = (N + 127) / 128;

    detect_idx_kernel<<<1, 1>>>(edge_idx, E, pflag);
    cudaMemsetAsync(pdeg, 0, (size_t)N * sizeof(float));
    deg_kernel<<<(E + 255) / 256, 256>>>(edge_idx, pflag, pdeg, E);
    invdeg_kernel<<<(N + 255) / 256, 256>>>(pdeg, pinv, pmask, N);
    encoder_kernel<<<(N * HID + 255) / 256, 256>>>(node_feat, enc_W, enc_b, px, N);

    for (int l = 0; l < 3; ++l) {
        const float* W1  = mlp_W1 + (size_t)l * 257 * HID;
        const float* W1a = W1;                       // dst part (rows 0..127)
        const float* W1b = W1 + 128 * HID;           // src part (rows 128..255)
        const float* cve = W1 + 256 * HID;           // edge_attr row (row 256)
        const float* b1  = mlp_b1 + (size_t)l * HID;
        const float* W2  = mlp_W2 + (size_t)l * HID * HID;
        const float* b2  = mlp_b2 + (size_t)l * HID;
        const float* U1a = upd_W1 + (size_t)l * 256 * HID;          // x part
        const float* U1b = U1a + 128 * HID;                         // aggr part
        const float* ub1 = upd_b1 + (size_t)l * HID;
        const float* U2  = upd_W2 + (size_t)l * HID * HID;
        const float* ub2 = upd_b2 + (size_t)l * HID;

        // A = x@W1a + b1 ; B = x@W1b
        sgemm128<<<gemm_grid, 256>>>(px, W1a, nullptr, nullptr, b1, nullptr, nullptr, pA, N, 0);
        sgemm128<<<gemm_grid, 256>>>(px, W1b, nullptr, nullptr, nullptr, nullptr, nullptr, pB, N, 0);

        // S = segment_sum(relu(A[dst]+B[src]+e*c), dst)
        cudaMemsetAsync(pS, 0, (size_t)N * HID * sizeof(float));
        edge_kernel<<<(E + 7) / 8, 256>>>(pA, pB, edge_attr, cve, edge_idx, pflag, pS, E);

        // aggr = (S*inv_deg)@W2 + b2*[deg>0]
        sgemm128<<<gemm_grid, 256>>>(pS, W2, nullptr, nullptr, b2, pinv, pmask, pT, N, 0);

        // h = relu(x@U1a + aggr@U1b + ub1)   -> reuse g_A
        sgemm128<<<gemm_grid, 256>>>(px, U1a, pT, U1b, ub1, nullptr, nullptr, pA, N, 1);

        // x_new = h@U2 + ub2                  -> reuse g_B
        sgemm128<<<gemm_grid, 256>>>(pA, U2, nullptr, nullptr, ub2, nullptr, nullptr, pB, N, 0);

        // x = relu(LN(x_new))
        ln_relu_kernel<<<(N * 32 + 255) / 256, 256>>>(pB, ln_g + (size_t)l * HID,
                                                      ln_b + (size_t)l * HID, px, N);
    }

    cudaMemsetAsync(pcs, 0, HID * sizeof(float));
    colsum_kernel<<<128, 256>>>(px, pcs, N);
    head_kernel<<<1, HID>>>(pcs, out_W1, out_b1, out_W2, out_b2,
                            (float*)d_out, 1.0f / (float)N);
}

// round 3
// speedup vs baseline: 1.2807x; 1.2807x over previous
#include <cuda_runtime.h>
#include <cuda_bf16.h>
#include <cstdint>

#define NNODES 50000
#define NEDGES 800000
#define HID    128

// ---------------- scratch (device globals; no allocation allowed) ----------
__device__ float g_x[NNODES * HID];
__device__ float g_A[NNODES * HID];
__device__ float g_B[NNODES * HID];
__device__ float g_S[NNODES * HID];
__device__ float g_T[NNODES * HID];
__device__ float g_deg[NNODES];
__device__ float g_inv[NNODES];
__device__ float g_mask[NNODES];
__device__ float g_colsum[HID];
__device__ int   g_is64;
// 18 weight slices (3 layers x {W1a,W1b,W2,U1a,U1b,U2}), each 128x128 bf16,
// stored transposed ([out][k], packed row-major), hi and lo parts.
__device__ __nv_bfloat16 g_Wh[18 * 16384];
__device__ __nv_bfloat16 g_Wl[18 * 16384];

// ---------------- helpers ----------------------------------------------------
__device__ __forceinline__ uint32_t smem_to_u32(const void* smem_ptr) {
    uint32_t addr;
    asm("{ .reg .u64 tmp; cvta.to.shared.u64 tmp, %1; cvt.u32.u64 %0, tmp; }"
        : "=r"(addr) : "l"(smem_ptr));
    return addr;
}
__device__ __forceinline__ uint32_t split_pair(float a, float b, uint32_t& lo) {
    __nv_bfloat16 ha = __float2bfloat16(a), hb = __float2bfloat16(b);
    __nv_bfloat16 la = __float2bfloat16(a - __bfloat162float(ha));
    __nv_bfloat16 lb = __float2bfloat16(b - __bfloat162float(hb));
    lo = (uint32_t)__bfloat16_as_ushort(la) | ((uint32_t)__bfloat16_as_ushort(lb) << 16);
    return (uint32_t)__bfloat16_as_ushort(ha) | ((uint32_t)__bfloat16_as_ushort(hb) << 16);
}
__device__ __forceinline__ void ldmatrix_x4(uint32_t& r0, uint32_t& r1,
                                            uint32_t& r2, uint32_t& r3, uint32_t addr) {
    asm volatile("ldmatrix.sync.aligned.m8n8.x4.shared.b16 {%0,%1,%2,%3}, [%4];"
                 : "=r"(r0), "=r"(r1), "=r"(r2), "=r"(r3) : "r"(addr));
}
__device__ __forceinline__ void mma16816(float* d, const uint32_t* a, const uint32_t* b) {
    asm volatile(
        "mma.sync.aligned.m16n8k16.row.col.f32.bf16.bf16.f32 "
        "{%0,%1,%2,%3}, {%4,%5,%6,%7}, {%8,%9}, {%0,%1,%2,%3};"
        : "+f"(d[0]), "+f"(d[1]), "+f"(d[2]), "+f"(d[3])
        : "r"(a[0]), "r"(a[1]), "r"(a[2]), "r"(a[3]), "r"(b[0]), "r"(b[1]));
}

// smem tile geometry: 128 rows x 128 bf16, padded to 136 bf16 (272B) per row
#define ROWB 272
#define TILE_BYTES (128 * ROWB)   // 34816

// ---------------- index dtype detection ------------------------------------
__global__ void detect_idx_kernel(const void* idx, int E, int* flag) {
    const long long* p = (const long long*)idx;
    int is64 = 1;
    int n = (E < 128) ? E : 128;
    for (int i = 0; i < n; ++i) {
        long long v = p[i];
        if (v < 0 || v >= NNODES) { is64 = 0; break; }
    }
    *flag = is64;
}
__device__ __forceinline__ int load_idx(const void* idx, int is64, long long pos) {
    if (is64) return (int)((const long long*)idx)[pos];
    return ((const int*)idx)[pos];
}

// ---------------- degree ----------------------------------------------------
__global__ void deg_kernel(const void* __restrict__ idx, const int* __restrict__ flag,
                           float* __restrict__ deg, int E) {
    int e = blockIdx.x * blockDim.x + threadIdx.x;
    if (e >= E) return;
    int dst = load_idx(idx, *flag, (long long)E + e);
    atomicAdd(&deg[dst], 1.0f);
}
__global__ void invdeg_kernel(const float* __restrict__ deg, float* __restrict__ inv,
                              float* __restrict__ mask, int N) {
    int i = blockIdx.x * blockDim.x + threadIdx.x;
    if (i >= N) return;
    float d = deg[i];
    inv[i]  = 1.0f / fmaxf(d, 1.0f);
    mask[i] = (d > 0.0f) ? 1.0f : 0.0f;
}

// ---------------- encoder ----------------------------------------------------
__global__ void encoder_kernel(const float* __restrict__ nf, const float* __restrict__ W,
                               const float* __restrict__ b, float* __restrict__ x, int N) {
    int i = blockIdx.x * blockDim.x + threadIdx.x;
    if (i >= N * HID) return;
    int n = i >> 7;
    int h = i & 127;
    float acc = b[h];
#pragma unroll
    for (int k = 0; k < 5; ++k)
        acc = fmaf(nf[n * 5 + k], W[k * HID + h], acc);
    x[i] = acc;
}

// ---------------- weight prep: transpose + bf16 hi/lo split (packed) -------
__global__ void prep_weights(const float* __restrict__ mlp_W1, const float* __restrict__ mlp_W2,
                             const float* __restrict__ upd_W1, const float* __restrict__ upd_W2,
                             __nv_bfloat16* __restrict__ Wh, __nv_bfloat16* __restrict__ Wl) {
    int s = blockIdx.x;            // 0..17
    int l = s / 6, j = s % 6;
    const float* src;
    switch (j) {
        case 0:  src = mlp_W1 + (size_t)l * 257 * 128; break;
        case 1:  src = mlp_W1 + (size_t)l * 257 * 128 + 128 * 128; break;
        case 2:  src = mlp_W2 + (size_t)l * 128 * 128; break;
        case 3:  src = upd_W1 + (size_t)l * 256 * 128; break;
        case 4:  src = upd_W1 + (size_t)l * 256 * 128 + 128 * 128; break;
        default: src = upd_W2 + (size_t)l * 128 * 128; break;
    }
    uint4* dh = reinterpret_cast<uint4*>(Wh + (size_t)s * 16384);
    uint4* dl = reinterpret_cast<uint4*>(Wl + (size_t)s * 16384);
    // 2048 16-byte chunks: chunk c -> out=c>>4, k0=(c&15)*8 ; dst packed [out][k]
    for (int c = threadIdx.x; c < 2048; c += blockDim.x) {
        int out = c >> 4, k0 = (c & 15) * 8;
        uint32_t hv[4], lv[4];
#pragma unroll
        for (int u = 0; u < 4; ++u) {
            float a = src[(size_t)(k0 + 2 * u) * 128 + out];
            float b = src[(size_t)(k0 + 2 * u + 1) * 128 + out];
            hv[u] = split_pair(a, b, lv[u]);
        }
        dh[c] = make_uint4(hv[0], hv[1], hv[2], hv[3]);
        dl[c] = make_uint4(lv[0], lv[1], lv[2], lv[3]);
    }
}

// ---------------- tensor-core GEMM via mma.sync ------------------------------
// C[M,128] = f( sum_slices A_s[M,128] @ W_s^T  (*rowscale rows)  + bias*biasmask )
// A fp32 in global; W as packed transposed bf16 hi/lo images. 2-term bf16 split
// -> 3 MMA passes per slice: Ah*Bh + Al*Bh + Ah*Bl.
__global__ __launch_bounds__(256) void mma_gemm(
    const float* __restrict__ A0,
    const __nv_bfloat16* __restrict__ B0h, const __nv_bfloat16* __restrict__ B0l,
    const float* __restrict__ A1,
    const __nv_bfloat16* __restrict__ B1h, const __nv_bfloat16* __restrict__ B1l,
    const float* __restrict__ bias, const float* __restrict__ rowscale,
    const float* __restrict__ biasmask,
    float* __restrict__ C, int M, int doRelu)
{
    extern __shared__ char sm[];
    char* Ah = sm;
    char* Al = sm + TILE_BYTES;
    char* Bh = sm + 2 * TILE_BYTES;
    char* Bl = sm + 3 * TILE_BYTES;
    const uint32_t sAh = smem_to_u32(Ah), sAl = smem_to_u32(Al);
    const uint32_t sBh = smem_to_u32(Bh), sBl = smem_to_u32(Bl);

    const int tid  = threadIdx.x;
    const int wid  = tid >> 5;
    const int lane = tid & 31;
    const int warp_m = wid & 3;    // 4 warps along M (32 rows each)
    const int warp_n = wid >> 2;   // 2 warps along N (64 cols each)
    const int m0 = blockIdx.x * 128;

    float acc[2][8][4];
#pragma unroll
    for (int i = 0; i < 2; ++i)
#pragma unroll
        for (int j = 0; j < 8; ++j)
#pragma unroll
            for (int k = 0; k < 4; ++k) acc[i][j][k] = 0.0f;

    // per-lane ldmatrix address offsets (bytes, within a tile)
    // A frag (m16k16): lanes0-7->m0-7 k0, 8-15->m8-15 k0, 16-23->m0-7 k8, 24-31->m8-15 k8
    uint32_t a_off[2];
#pragma unroll
    for (int mt = 0; mt < 2; ++mt)
        a_off[mt] = (uint32_t)((warp_m * 32 + mt * 16 + (lane & 15)) * ROWB
                               + (lane >> 4) * 16);
    // B frag (two n8 tiles per x4): lanes0-7->n0-7 k0, 8-15->n0-7 k8, 16-23->n8-15 k0, 24-31->n8-15 k8
    uint32_t b_off[4];
#pragma unroll
    for (int bt = 0; bt < 4; ++bt)
        b_off[bt] = (uint32_t)((warp_n * 64 + bt * 16 + ((lane >> 4) & 1) * 8 + (lane & 7)) * ROWB
                               + ((lane >> 3) & 1) * 16);

    const int nsl = (A1 != nullptr) ? 2 : 1;
    for (int s = 0; s < nsl; ++s) {
        const float* A = s ? A1 : A0;
        const uint4* gBh = reinterpret_cast<const uint4*>(s ? B1h : B0h);
        const uint4* gBl = reinterpret_cast<const uint4*>(s ? B1l : B0l);

        __syncthreads();   // previous pass reads complete before refill
        // fill B tiles (straight copy with 272B restride)
#pragma unroll
        for (int i = 0; i < 8; ++i) {
            int cidx = tid + i * 256;
            int row = cidx >> 4, c = cidx & 15;
            uint32_t off = (uint32_t)(row * ROWB + c * 16);
            *reinterpret_cast<uint4*>(Bh + off) = gBh[cidx];
            *reinterpret_cast<uint4*>(Bl + off) = gBl[cidx];
        }
        // fill A tiles (fp32 -> hi/lo split)
#pragma unroll
        for (int i = 0; i < 8; ++i) {
            int cidx = tid + i * 256;
            int row = cidx >> 4, c = cidx & 15;
            int arow = m0 + row;
            int k0 = c * 8;
            uint32_t off = (uint32_t)(row * ROWB + c * 16);
            uint4 hv4 = make_uint4(0u, 0u, 0u, 0u), lv4 = make_uint4(0u, 0u, 0u, 0u);
            if (arow < M) {
                float4 v0 = *reinterpret_cast<const float4*>(A + (size_t)arow * HID + k0);
                float4 v1 = *reinterpret_cast<const float4*>(A + (size_t)arow * HID + k0 + 4);
                if (rowscale != nullptr) {
                    float rs = rowscale[arow];
                    v0.x *= rs; v0.y *= rs; v0.z *= rs; v0.w *= rs;
                    v1.x *= rs; v1.y *= rs; v1.z *= rs; v1.w *= rs;
                }
                uint32_t lo;
                hv4.x = split_pair(v0.x, v0.y, lo); lv4.x = lo;
                hv4.y = split_pair(v0.z, v0.w, lo); lv4.y = lo;
                hv4.z = split_pair(v1.x, v1.y, lo); lv4.z = lo;
                hv4.w = split_pair(v1.z, v1.w, lo); lv4.w = lo;
            }
            *reinterpret_cast<uint4*>(Ah + off) = hv4;
            *reinterpret_cast<uint4*>(Al + off) = lv4;
        }
        __syncthreads();

        // 3 split passes: Ah*Bh, Al*Bh, Ah*Bl
        uint32_t pa[3] = { sAh, sAl, sAh };
        uint32_t pb[3] = { sBh, sBh, sBl };
#pragma unroll
        for (int p = 0; p < 3; ++p) {
            uint32_t abase = pa[p], bbase = pb[p];
#pragma unroll
            for (int kk = 0; kk < 8; ++kk) {
                uint32_t a[2][4];
                uint32_t b[8][2];
#pragma unroll
                for (int mt = 0; mt < 2; ++mt)
                    ldmatrix_x4(a[mt][0], a[mt][1], a[mt][2], a[mt][3],
                                abase + a_off[mt] + kk * 32);
#pragma unroll
                for (int bt = 0; bt < 4; ++bt)
                    ldmatrix_x4(b[2 * bt][0], b[2 * bt][1], b[2 * bt + 1][0], b[2 * bt + 1][1],
                                bbase + b_off[bt] + kk * 32);
#pragma unroll
                for (int mt = 0; mt < 2; ++mt)
#pragma unroll
                    for (int nt = 0; nt < 8; ++nt)
                        mma16816(acc[mt][nt], a[mt], b[nt]);
            }
        }
    }

    // epilogue: thread holds (row = base + lane>>2 [+8], cols = nbase + (lane&3)*2 +{0,1})
#pragma unroll
    for (int mt = 0; mt < 2; ++mt) {
        int r0 = m0 + warp_m * 32 + mt * 16 + (lane >> 2);
#pragma unroll
        for (int half = 0; half < 2; ++half) {
            int r = r0 + half * 8;
            if (r >= M) continue;
            float bm = 1.0f;
            if (biasmask != nullptr) bm = biasmask[r];
#pragma unroll
            for (int nt = 0; nt < 8; ++nt) {
                int col = warp_n * 64 + nt * 8 + (lane & 3) * 2;
                float v0 = acc[mt][nt][2 * half + 0];
                float v1 = acc[mt][nt][2 * half + 1];
                if (bias != nullptr) {
                    v0 = fmaf(bm, bias[col + 0], v0);
                    v1 = fmaf(bm, bias[col + 1], v1);
                }
                if (doRelu) { v0 = fmaxf(v0, 0.0f); v1 = fmaxf(v1, 0.0f); }
                *reinterpret_cast<float2*>(C + (size_t)r * HID + col) = make_float2(v0, v1);
            }
        }
    }
}

// ---------------- edge kernel: S[dst] += relu(A[dst] + B[src] + e*c) --------
__global__ __launch_bounds__(256) void edge_kernel(
    const float* __restrict__ A, const float* __restrict__ B,
    const float* __restrict__ eattr, const float* __restrict__ cvec,
    const void* __restrict__ eidx, const int* __restrict__ flag,
    float* __restrict__ S, int E)
{
    int e = (blockIdx.x << 3) + (threadIdx.x >> 5);
    if (e >= E) return;
    int lane = threadIdx.x & 31;
    int is64 = *flag;
    int src = load_idx(eidx, is64, e);
    int dst = load_idx(eidx, is64, (long long)E + e);
    float ea = eattr[e];
    const float4 a = *reinterpret_cast<const float4*>(A + (size_t)dst * HID + lane * 4);
    const float4 b = *reinterpret_cast<const float4*>(B + (size_t)src * HID + lane * 4);
    const float4 c = *reinterpret_cast<const float4*>(cvec + lane * 4);
    float4 v;
    v.x = fmaxf(fmaf(ea, c.x, a.x + b.x), 0.0f);
    v.y = fmaxf(fmaf(ea, c.y, a.y + b.y), 0.0f);
    v.z = fmaxf(fmaf(ea, c.z, a.z + b.z), 0.0f);
    v.w = fmaxf(fmaf(ea, c.w, a.w + b.w), 0.0f);
    float* sp = S + (size_t)dst * HID + lane * 4;
    atomicAdd(sp + 0, v.x);
    atomicAdd(sp + 1, v.y);
    atomicAdd(sp + 2, v.z);
    atomicAdd(sp + 3, v.w);
}

// ---------------- LayerNorm + ReLU ------------------------------------------
__global__ __launch_bounds__(256) void ln_relu_kernel(
    const float* __restrict__ in, const float* __restrict__ g,
    const float* __restrict__ b, float* __restrict__ out, int N)
{
    int node = (blockIdx.x * blockDim.x + threadIdx.x) >> 5;
    if (node >= N) return;
    int lane = threadIdx.x & 31;
    float4 v = *reinterpret_cast<const float4*>(in + (size_t)node * HID + lane * 4);
    float s = v.x + v.y + v.z + v.w;
#pragma unroll
    for (int o = 16; o > 0; o >>= 1) s += __shfl_xor_sync(0xffffffffu, s, o);
    float mu = s * (1.0f / 128.0f);
    float dx = v.x - mu, dy = v.y - mu, dz = v.z - mu, dw = v.w - mu;
    float q = dx * dx + dy * dy + dz * dz + dw * dw;
#pragma unroll
    for (int o = 16; o > 0; o >>= 1) q += __shfl_xor_sync(0xffffffffu, q, o);
    float rsd = rsqrtf(q * (1.0f / 128.0f) + 1e-5f);
    float4 gg = *reinterpret_cast<const float4*>(g + lane * 4);
    float4 bb = *reinterpret_cast<const float4*>(b + lane * 4);
    float4 r;
    r.x = fmaxf(fmaf(dx * rsd, gg.x, bb.x), 0.0f);
    r.y = fmaxf(fmaf(dy * rsd, gg.y, bb.y), 0.0f);
    r.z = fmaxf(fmaf(dz * rsd, gg.z, bb.z), 0.0f);
    r.w = fmaxf(fmaf(dw * rsd, gg.w, bb.w), 0.0f);
    *reinterpret_cast<float4*>(out + (size_t)node * HID + lane * 4) = r;
}

// ---------------- column sum -------------------------------------------------
__global__ void colsum_kernel(const float* __restrict__ x, float* __restrict__ cs, int N) {
    int col = threadIdx.x & 127;
    int rg  = threadIdx.x >> 7;
    float s = 0.0f;
    for (int row = blockIdx.x * 2 + rg; row < N; row += gridDim.x * 2)
        s += x[(size_t)row * HID + col];
    atomicAdd(&cs[col], s);
}

// ---------------- output head ------------------------------------------------
__global__ void head_kernel(const float* __restrict__ cs,
                            const float* __restrict__ W1, const float* __restrict__ b1,
                            const float* __restrict__ W2, const float* __restrict__ b2,
                            float* __restrict__ out, float invN)
{
    __shared__ float g[HID], h[HID];
    int t = threadIdx.x;
    g[t] = cs[t] * invN;
    __syncthreads();
    float acc = b1[t];
#pragma unroll 8
    for (int k = 0; k < HID; ++k) acc = fmaf(g[k], W1[k * HID + t], acc);
    h[t] = fmaxf(acc, 0.0f);
    __syncthreads();
    float o = b2[t];
#pragma unroll 8
    for (int k = 0; k < HID; ++k) o = fmaf(h[k], W2[k * HID + t], o);
    out[t] = o;
}

// ---------------- launch ----------------------------------------------------
extern "C" void kernel_launch(void* const* d_in, const int* in_sizes, int n_in,
                              void* d_out, int out_size) {
    const float* node_feat = (const float*)d_in[0];
    const float* edge_attr = (const float*)d_in[1];
    const float* enc_W     = (const float*)d_in[2];
    const float* enc_b     = (const float*)d_in[3];
    const float* mlp_W1    = (const float*)d_in[4];
    const float* mlp_b1    = (const float*)d_in[5];
    const float* mlp_W2    = (const float*)d_in[6];
    const float* mlp_b2    = (const float*)d_in[7];
    const float* upd_W1    = (const float*)d_in[8];
    const float* upd_b1    = (const float*)d_in[9];
    const float* upd_W2    = (const float*)d_in[10];
    const float* upd_b2    = (const float*)d_in[11];
    const float* ln_g      = (const float*)d_in[12];
    const float* ln_b      = (const float*)d_in[13];
    const float* out_W1    = (const float*)d_in[14];
    const float* out_b1    = (const float*)d_in[15];
    const float* out_W2    = (const float*)d_in[16];
    const float* out_b2    = (const float*)d_in[17];
    const void*  edge_idx  = d_in[18];

    const int N = in_sizes[0] / 5;
    const int E = in_sizes[18] / 2;

    float *px, *pA, *pB, *pS, *pT, *pdeg, *pinv, *pmask, *pcs;
    int* pflag;
    __nv_bfloat16 *pWh, *pWl;
    cudaGetSymbolAddress((void**)&px,    g_x);
    cudaGetSymbolAddress((void**)&pA,    g_A);
    cudaGetSymbolAddress((void**)&pB,    g_B);
    cudaGetSymbolAddress((void**)&pS,    g_S);
    cudaGetSymbolAddress((void**)&pT,    g_T);
    cudaGetSymbolAddress((void**)&pdeg,  g_deg);
    cudaGetSymbolAddress((void**)&pinv,  g_inv);
    cudaGetSymbolAddress((void**)&pmask, g_mask);
    cudaGetSymbolAddress((void**)&pcs,   g_colsum);
    cudaGetSymbolAddress((void**)&pflag, g_is64);
    cudaGetSymbolAddress((void**)&pWh,   g_Wh);
    cudaGetSymbolAddress((void**)&pWl,   g_Wl);

    const int DSMEM = 4 * TILE_BYTES;   // 139264 bytes
    static int attr_set = 0;
    cudaFuncSetAttribute(mma_gemm, cudaFuncAttributeMaxDynamicSharedMemorySize, DSMEM);
    (void)attr_set;

    const int gemm_grid = (N + 127) / 128;

    detect_idx_kernel<<<1, 1>>>(edge_idx, E, pflag);
    cudaMemsetAsync(pdeg, 0, (size_t)N * sizeof(float));
    deg_kernel<<<(E + 255) / 256, 256>>>(edge_idx, pflag, pdeg, E);
    invdeg_kernel<<<(N + 255) / 256, 256>>>(pdeg, pinv, pmask, N);
    encoder_kernel<<<(N * HID + 255) / 256, 256>>>(node_feat, enc_W, enc_b, px, N);
    prep_weights<<<18, 256>>>(mlp_W1, mlp_W2, upd_W1, upd_W2, pWh, pWl);

    for (int l = 0; l < 3; ++l) {
        const float* cve = mlp_W1 + (size_t)l * 257 * HID + 256 * HID; // edge_attr row
        const float* b1  = mlp_b1 + (size_t)l * HID;
        const float* b2  = mlp_b2 + (size_t)l * HID;
        const float* ub1 = upd_b1 + (size_t)l * HID;
        const float* ub2 = upd_b2 + (size_t)l * HID;
        __nv_bfloat16* W1a_h = pWh + (size_t)(l * 6 + 0) * 16384;
        __nv_bfloat16* W1a_l = pWl + (size_t)(l * 6 + 0) * 16384;
        __nv_bfloat16* W1b_h = pWh + (size_t)(l * 6 + 1) * 16384;
        __nv_bfloat16* W1b_l = pWl + (size_t)(l * 6 + 1) * 16384;
        __nv_bfloat16* W2_h  = pWh + (size_t)(l * 6 + 2) * 16384;
        __nv_bfloat16* W2_l  = pWl + (size_t)(l * 6 + 2) * 16384;
        __nv_bfloat16* U1a_h = pWh + (size_t)(l * 6 + 3) * 16384;
        __nv_bfloat16* U1a_l = pWl + (size_t)(l * 6 + 3) * 16384;
        __nv_bfloat16* U1b_h = pWh + (size_t)(l * 6 + 4) * 16384;
        __nv_bfloat16* U1b_l = pWl + (size_t)(l * 6 + 4) * 16384;
        __nv_bfloat16* U2_h  = pWh + (size_t)(l * 6 + 5) * 16384;
        __nv_bfloat16* U2_l  = pWl + (size_t)(l * 6 + 5) * 16384;

        // A_msg = x@W1a + b1 ; B_msg = x@W1b
        mma_gemm<<<gemm_grid, 256, DSMEM>>>(px, W1a_h, W1a_l, nullptr, nullptr, nullptr,
                                            b1, nullptr, nullptr, pA, N, 0);
        mma_gemm<<<gemm_grid, 256, DSMEM>>>(px, W1b_h, W1b_l, nullptr, nullptr, nullptr,
                                            nullptr, nullptr, nullptr, pB, N, 0);

        // S = segment_sum(relu(A[dst]+B[src]+e*c), dst)
        cudaMemsetAsync(pS, 0, (size_t)N * HID * sizeof(float));
        edge_kernel<<<(E + 7) / 8, 256>>>(pA, pB, edge_attr, cve, edge_idx, pflag, pS, E);

        // aggr = (S*inv_deg)@W2 + b2*[deg>0]
        mma_gemm<<<gemm_grid, 256, DSMEM>>>(pS, W2_h, W2_l, nullptr, nullptr, nullptr,
                                            b2, pinv, pmask, pT, N, 0);

        // h = relu(x@U1a + aggr@U1b + ub1)
        mma_gemm<<<gemm_grid, 256, DSMEM>>>(px, U1a_h, U1a_l, pT, U1b_h, U1b_l,
                                            ub1, nullptr, nullptr, pA, N, 1);

        // x_new = h@U2 + ub2
        mma_gemm<<<gemm_grid, 256, DSMEM>>>(pA, U2_h, U2_l, nullptr, nullptr, nullptr,
                                            ub2, nullptr, nullptr, pB, N, 0);

        // x = relu(LN(x_new))
        ln_relu_kernel<<<(N * 32 + 255) / 256, 256>>>(pB, ln_g + (size_t)l * HID,
                                                      ln_b + (size_t)l * HID, px, N);
    }

    cudaMemsetAsync(pcs, 0, HID * sizeof(float));
    colsum_kernel<<<128, 256>>>(px, pcs, N);
    head_kernel<<<1, HID>>>(pcs, out_W1, out_b1, out_W2, out_b2,
                            (float*)d_out, 1.0f / (float)N);
}

// round 5
// speedup vs baseline: 2.1620x; 1.6882x over previous
#include <cuda_runtime.h>
#include <cuda_bf16.h>
#include <cstdint>

#define NNODES 50000
#define NEDGES 800000
#define HID    128

// ---------------- scratch (device globals; no allocation allowed) ----------
__device__ float g_x[NNODES * HID];
__device__ float g_A[NNODES * HID];
__device__ float g_B[NNODES * HID];
__device__ float g_S[NNODES * HID];
__device__ float g_T[NNODES * HID];
__device__ float g_inv[NNODES];
__device__ float g_mask[NNODES];
__device__ float g_colsum[HID];
__device__ int   g_is64;
// CSR by dst
__device__ int   g_cnt[NNODES];
__device__ int   g_off[NNODES + 1];
__device__ int   g_cur[NNODES];
__device__ int   g_bsum[64];
__device__ int   g_srcs[NEDGES];
__device__ float g_eas[NEDGES];
// 18 weight slices (3 layers x {W1a,W1b,W2,U1a,U1b,U2}), each 128x128 bf16,
// stored transposed ([out][k], packed row-major), hi and lo parts.
__device__ __nv_bfloat16 g_Wh[18 * 16384];
__device__ __nv_bfloat16 g_Wl[18 * 16384];

// ---------------- helpers ----------------------------------------------------
__device__ __forceinline__ uint32_t smem_to_u32(const void* smem_ptr) {
    uint32_t addr;
    asm("{ .reg .u64 tmp; cvta.to.shared.u64 tmp, %1; cvt.u32.u64 %0, tmp; }"
        : "=r"(addr) : "l"(smem_ptr));
    return addr;
}
__device__ __forceinline__ uint32_t split_pair(float a, float b, uint32_t& lo) {
    __nv_bfloat16 ha = __float2bfloat16(a), hb = __float2bfloat16(b);
    __nv_bfloat16 la = __float2bfloat16(a - __bfloat162float(ha));
    __nv_bfloat16 lb = __float2bfloat16(b - __bfloat162float(hb));
    lo = (uint32_t)__bfloat16_as_ushort(la) | ((uint32_t)__bfloat16_as_ushort(lb) << 16);
    return (uint32_t)__bfloat16_as_ushort(ha) | ((uint32_t)__bfloat16_as_ushort(hb) << 16);
}
__device__ __forceinline__ void ldmatrix_x4(uint32_t& r0, uint32_t& r1,
                                            uint32_t& r2, uint32_t& r3, uint32_t addr) {
    asm volatile("ldmatrix.sync.aligned.m8n8.x4.shared.b16 {%0,%1,%2,%3}, [%4];"
                 : "=r"(r0), "=r"(r1), "=r"(r2), "=r"(r3) : "r"(addr));
}
__device__ __forceinline__ void mma16816(float* d, const uint32_t* a, const uint32_t* b) {
    asm volatile(
        "mma.sync.aligned.m16n8k16.row.col.f32.bf16.bf16.f32 "
        "{%0,%1,%2,%3}, {%4,%5,%6,%7}, {%8,%9}, {%0,%1,%2,%3};"
        : "+f"(d[0]), "+f"(d[1]), "+f"(d[2]), "+f"(d[3])
        : "r"(a[0]), "r"(a[1]), "r"(a[2]), "r"(a[3]), "r"(b[0]), "r"(b[1]));
}

#define ROWB 272
#define TILE_BYTES (128 * ROWB)   // 34816

// ---------------- index dtype detection ------------------------------------
__global__ void detect_idx_kernel(const void* idx, int E, int* flag) {
    const long long* p = (const long long*)idx;
    int is64 = 1;
    int n = (E < 128) ? E : 128;
    for (int i = 0; i < n; ++i) {
        long long v = p[i];
        if (v < 0 || v >= NNODES) { is64 = 0; break; }
    }
    *flag = is64;
}
__device__ __forceinline__ int load_idx(const void* idx, int is64, long long pos) {
    if (is64) return (int)((const long long*)idx)[pos];
    return ((const int*)idx)[pos];
}

// ---------------- CSR build --------------------------------------------------
__global__ void hist_kernel(const void* __restrict__ idx, const int* __restrict__ flag,
                            int* __restrict__ cnt, int E) {
    int e = blockIdx.x * blockDim.x + threadIdx.x;
    if (e >= E) return;
    int dst = load_idx(idx, *flag, (long long)E + e);
    atomicAdd(&cnt[dst], 1);
}
__global__ void scan1_kernel(const int* __restrict__ cnt, int* __restrict__ off,
                             int* __restrict__ bsum, int N) {
    __shared__ int sm[1024];
    int i = blockIdx.x * 1024 + threadIdx.x;
    int v = (i < N) ? cnt[i] : 0;
    sm[threadIdx.x] = v;
    __syncthreads();
#pragma unroll
    for (int o = 1; o < 1024; o <<= 1) {
        int t = (threadIdx.x >= o) ? sm[threadIdx.x - o] : 0;
        __syncthreads();
        sm[threadIdx.x] += t;
        __syncthreads();
    }
    if (i < N) off[i] = sm[threadIdx.x] - v;   // exclusive
    if (threadIdx.x == 1023) bsum[blockIdx.x] = sm[1023];
}
__global__ void scan2_kernel(int* bsum, int nb) {
    if (threadIdx.x == 0) {
        int run = 0;
        for (int b = 0; b < nb; ++b) { int t = bsum[b]; bsum[b] = run; run += t; }
    }
}
__global__ void scan3_kernel(int* __restrict__ off, int* __restrict__ cur,
                             const int* __restrict__ bsum,
                             const int* __restrict__ cnt,
                             float* __restrict__ inv, float* __restrict__ mask,
                             int N, int E) {
    int i = blockIdx.x * blockDim.x + threadIdx.x;
    if (i == 0) off[N] = E;
    if (i >= N) return;
    int o = off[i] + bsum[i >> 10];
    off[i] = o;
    cur[i] = o;
    int c = cnt[i];
    inv[i]  = 1.0f / (float)((c > 1) ? c : 1);
    mask[i] = (c > 0) ? 1.0f : 0.0f;
}
__global__ void scatter_kernel(const void* __restrict__ idx, const int* __restrict__ flag,
                               const float* __restrict__ eattr,
                               int* __restrict__ cur, int* __restrict__ srcs,
                               float* __restrict__ eas, int E) {
    int e = blockIdx.x * blockDim.x + threadIdx.x;
    if (e >= E) return;
    int is64 = *flag;
    int src = load_idx(idx, is64, e);
    int dst = load_idx(idx, is64, (long long)E + e);
    int p = atomicAdd(&cur[dst], 1);
    srcs[p] = src;
    eas[p]  = eattr[e];
}

// ---------------- encoder ----------------------------------------------------
__global__ void encoder_kernel(const float* __restrict__ nf, const float* __restrict__ W,
                               const float* __restrict__ b, float* __restrict__ x, int N) {
    int i = blockIdx.x * blockDim.x + threadIdx.x;
    if (i >= N * HID) return;
    int n = i >> 7;
    int h = i & 127;
    float acc = b[h];
#pragma unroll
    for (int k = 0; k < 5; ++k)
        acc = fmaf(nf[n * 5 + k], W[k * HID + h], acc);
    x[i] = acc;
}

// ---------------- weight prep: transpose + bf16 hi/lo split (packed) -------
__global__ void prep_weights(const float* __restrict__ mlp_W1, const float* __restrict__ mlp_W2,
                             const float* __restrict__ upd_W1, const float* __restrict__ upd_W2,
                             __nv_bfloat16* __restrict__ Wh, __nv_bfloat16* __restrict__ Wl) {
    int s = blockIdx.x;            // 0..17
    int l = s / 6, j = s % 6;
    const float* src;
    switch (j) {
        case 0:  src = mlp_W1 + (size_t)l * 257 * 128; break;
        case 1:  src = mlp_W1 + (size_t)l * 257 * 128 + 128 * 128; break;
        case 2:  src = mlp_W2 + (size_t)l * 128 * 128; break;
        case 3:  src = upd_W1 + (size_t)l * 256 * 128; break;
        case 4:  src = upd_W1 + (size_t)l * 256 * 128 + 128 * 128; break;
        default: src = upd_W2 + (size_t)l * 128 * 128; break;
    }
    uint4* dh = reinterpret_cast<uint4*>(Wh + (size_t)s * 16384);
    uint4* dl = reinterpret_cast<uint4*>(Wl + (size_t)s * 16384);
    for (int c = threadIdx.x; c < 2048; c += blockDim.x) {
        int out = c >> 4, k0 = (c & 15) * 8;
        uint32_t hv[4], lv[4];
#pragma unroll
        for (int u = 0; u < 4; ++u) {
            float a = src[(size_t)(k0 + 2 * u) * 128 + out];
            float b = src[(size_t)(k0 + 2 * u + 1) * 128 + out];
            hv[u] = split_pair(a, b, lv[u]);
        }
        dh[c] = make_uint4(hv[0], hv[1], hv[2], hv[3]);
        dl[c] = make_uint4(lv[0], lv[1], lv[2], lv[3]);
    }
}

// ---------------- tensor-core GEMM via mma.sync ------------------------------
__global__ __launch_bounds__(256) void mma_gemm(
    const float* __restrict__ A0,
    const __nv_bfloat16* __restrict__ B0h, const __nv_bfloat16* __restrict__ B0l,
    const float* __restrict__ A1,
    const __nv_bfloat16* __restrict__ B1h, const __nv_bfloat16* __restrict__ B1l,
    const float* __restrict__ bias, const float* __restrict__ rowscale,
    const float* __restrict__ biasmask,
    float* __restrict__ C, int M, int doRelu)
{
    extern __shared__ char sm[];
    char* Ah = sm;
    char* Al = sm + TILE_BYTES;
    char* Bh = sm + 2 * TILE_BYTES;
    char* Bl = sm + 3 * TILE_BYTES;
    const uint32_t sAh = smem_to_u32(Ah), sAl = smem_to_u32(Al);
    const uint32_t sBh = smem_to_u32(Bh), sBl = smem_to_u32(Bl);

    const int tid  = threadIdx.x;
    const int wid  = tid >> 5;
    const int lane = tid & 31;
    const int warp_m = wid & 3;
    const int warp_n = wid >> 2;
    const int m0 = blockIdx.x * 128;

    float acc[2][8][4];
#pragma unroll
    for (int i = 0; i < 2; ++i)
#pragma unroll
        for (int j = 0; j < 8; ++j)
#pragma unroll
            for (int k = 0; k < 4; ++k) acc[i][j][k] = 0.0f;

    uint32_t a_off[2];
#pragma unroll
    for (int mt = 0; mt < 2; ++mt)
        a_off[mt] = (uint32_t)((warp_m * 32 + mt * 16 + (lane & 15)) * ROWB
                               + (lane >> 4) * 16);
    uint32_t b_off[4];
#pragma unroll
    for (int bt = 0; bt < 4; ++bt)
        b_off[bt] = (uint32_t)((warp_n * 64 + bt * 16 + ((lane >> 4) & 1) * 8 + (lane & 7)) * ROWB
                               + ((lane >> 3) & 1) * 16);

    const int nsl = (A1 != nullptr) ? 2 : 1;
    for (int s = 0; s < nsl; ++s) {
        const float* A = s ? A1 : A0;
        const uint4* gBh = reinterpret_cast<const uint4*>(s ? B1h : B0h);
        const uint4* gBl = reinterpret_cast<const uint4*>(s ? B1l : B0l);

        __syncthreads();
#pragma unroll
        for (int i = 0; i < 8; ++i) {
            int cidx = tid + i * 256;
            int row = cidx >> 4, c = cidx & 15;
            uint32_t off = (uint32_t)(row * ROWB + c * 16);
            *reinterpret_cast<uint4*>(Bh + off) = gBh[cidx];
            *reinterpret_cast<uint4*>(Bl + off) = gBl[cidx];
        }
#pragma unroll
        for (int i = 0; i < 8; ++i) {
            int cidx = tid + i * 256;
            int row = cidx >> 4, c = cidx & 15;
            int arow = m0 + row;
            int k0 = c * 8;
            uint32_t off = (uint32_t)(row * ROWB + c * 16);
            uint4 hv4 = make_uint4(0u, 0u, 0u, 0u), lv4 = make_uint4(0u, 0u, 0u, 0u);
            if (arow < M) {
                float4 v0 = *reinterpret_cast<const float4*>(A + (size_t)arow * HID + k0);
                float4 v1 = *reinterpret_cast<const float4*>(A + (size_t)arow * HID + k0 + 4);
                if (rowscale != nullptr) {
                    float rs = rowscale[arow];
                    v0.x *= rs; v0.y *= rs; v0.z *= rs; v0.w *= rs;
                    v1.x *= rs; v1.y *= rs; v1.z *= rs; v1.w *= rs;
                }
                uint32_t lo;
                hv4.x = split_pair(v0.x, v0.y, lo); lv4.x = lo;
                hv4.y = split_pair(v0.z, v0.w, lo); lv4.y = lo;
                hv4.z = split_pair(v1.x, v1.y, lo); lv4.z = lo;
                hv4.w = split_pair(v1.z, v1.w, lo); lv4.w = lo;
            }
            *reinterpret_cast<uint4*>(Ah + off) = hv4;
            *reinterpret_cast<uint4*>(Al + off) = lv4;
        }
        __syncthreads();

        uint32_t pa[3] = { sAh, sAl, sAh };
        uint32_t pb[3] = { sBh, sBh, sBl };
#pragma unroll
        for (int p = 0; p < 3; ++p) {
            uint32_t abase = pa[p], bbase = pb[p];
#pragma unroll
            for (int kk = 0; kk < 8; ++kk) {
                uint32_t a[2][4];
                uint32_t b[8][2];
#pragma unroll
                for (int mt = 0; mt < 2; ++mt)
                    ldmatrix_x4(a[mt][0], a[mt][1], a[mt][2], a[mt][3],
                                abase + a_off[mt] + kk * 32);
#pragma unroll
                for (int bt = 0; bt < 4; ++bt)
                    ldmatrix_x4(b[2 * bt][0], b[2 * bt][1], b[2 * bt + 1][0], b[2 * bt + 1][1],
                                bbase + b_off[bt] + kk * 32);
#pragma unroll
                for (int mt = 0; mt < 2; ++mt)
#pragma unroll
                    for (int nt = 0; nt < 8; ++nt)
                        mma16816(acc[mt][nt], a[mt], b[nt]);
            }
        }
    }

#pragma unroll
    for (int mt = 0; mt < 2; ++mt) {
        int r0 = m0 + warp_m * 32 + mt * 16 + (lane >> 2);
#pragma unroll
        for (int half = 0; half < 2; ++half) {
            int r = r0 + half * 8;
            if (r >= M) continue;
            float bm = 1.0f;
            if (biasmask != nullptr) bm = biasmask[r];
#pragma unroll
            for (int nt = 0; nt < 8; ++nt) {
                int col = warp_n * 64 + nt * 8 + (lane & 3) * 2;
                float v0 = acc[mt][nt][2 * half + 0];
                float v1 = acc[mt][nt][2 * half + 1];
                if (bias != nullptr) {
                    v0 = fmaf(bm, bias[col + 0], v0);
                    v1 = fmaf(bm, bias[col + 1], v1);
                }
                if (doRelu) { v0 = fmaxf(v0, 0.0f); v1 = fmaxf(v1, 0.0f); }
                *reinterpret_cast<float2*>(C + (size_t)r * HID + col) = make_float2(v0, v1);
            }
        }
    }
}

// ---------------- CSR aggregation: S[i] = sum_{e in adj(i)} relu(A[i]+B[src]+ea*c)
__global__ __launch_bounds__(256) void agg_kernel(
    const float* __restrict__ A, const float* __restrict__ B,
    const int* __restrict__ srcs, const float* __restrict__ eas,
    const int* __restrict__ off, const float* __restrict__ cvec,
    float* __restrict__ S, int N)
{
    int node = (blockIdx.x * blockDim.x + threadIdx.x) >> 5;
    if (node >= N) return;
    int lane = threadIdx.x & 31;
    const float4 a = *reinterpret_cast<const float4*>(A + (size_t)node * HID + lane * 4);
    const float4 c = *reinterpret_cast<const float4*>(cvec + lane * 4);
    float4 s = make_float4(0.f, 0.f, 0.f, 0.f);
    int p  = off[node];
    int pe = off[node + 1];
    for (; p + 1 < pe; p += 2) {
        int s0 = srcs[p], s1 = srcs[p + 1];
        float e0 = eas[p], e1 = eas[p + 1];
        const float4 b0 = *reinterpret_cast<const float4*>(B + (size_t)s0 * HID + lane * 4);
        const float4 b1 = *reinterpret_cast<const float4*>(B + (size_t)s1 * HID + lane * 4);
        s.x += fmaxf(fmaf(e0, c.x, a.x + b0.x), 0.0f) + fmaxf(fmaf(e1, c.x, a.x + b1.x), 0.0f);
        s.y += fmaxf(fmaf(e0, c.y, a.y + b0.y), 0.0f) + fmaxf(fmaf(e1, c.y, a.y + b1.y), 0.0f);
        s.z += fmaxf(fmaf(e0, c.z, a.z + b0.z), 0.0f) + fmaxf(fmaf(e1, c.z, a.z + b1.z), 0.0f);
        s.w += fmaxf(fmaf(e0, c.w, a.w + b0.w), 0.0f) + fmaxf(fmaf(e1, c.w, a.w + b1.w), 0.0f);
    }
    if (p < pe) {
        int s0 = srcs[p];
        float e0 = eas[p];
        const float4 b0 = *reinterpret_cast<const float4*>(B + (size_t)s0 * HID + lane * 4);
        s.x += fmaxf(fmaf(e0, c.x, a.x + b0.x), 0.0f);
        s.y += fmaxf(fmaf(e0, c.y, a.y + b0.y), 0.0f);
        s.z += fmaxf(fmaf(e0, c.z, a.z + b0.z), 0.0f);
        s.w += fmaxf(fmaf(e0, c.w, a.w + b0.w), 0.0f);
    }
    *reinterpret_cast<float4*>(S + (size_t)node * HID + lane * 4) = s;
}

// ---------------- LayerNorm + ReLU ------------------------------------------
__global__ __launch_bounds__(256) void ln_relu_kernel(
    const float* __restrict__ in, const float* __restrict__ g,
    const float* __restrict__ b, float* __restrict__ out, int N)
{
    int node = (blockIdx.x * blockDim.x + threadIdx.x) >> 5;
    if (node >= N) return;
    int lane = threadIdx.x & 31;
    float4 v = *reinterpret_cast<const float4*>(in + (size_t)node * HID + lane * 4);
    float s = v.x + v.y + v.z + v.w;
#pragma unroll
    for (int o = 16; o > 0; o >>= 1) s += __shfl_xor_sync(0xffffffffu, s, o);
    float mu = s * (1.0f / 128.0f);
    float dx = v.x - mu, dy = v.y - mu, dz = v.z - mu, dw = v.w - mu;
    float q = dx * dx + dy * dy + dz * dz + dw * dw;
#pragma unroll
    for (int o = 16; o > 0; o >>= 1) q += __shfl_xor_sync(0xffffffffu, q, o);
    float rsd = rsqrtf(q * (1.0f / 128.0f) + 1e-5f);
    float4 gg = *reinterpret_cast<const float4*>(g + lane * 4);
    float4 bb = *reinterpret_cast<const float4*>(b + lane * 4);
    float4 r;
    r.x = fmaxf(fmaf(dx * rsd, gg.x, bb.x), 0.0f);
    r.y = fmaxf(fmaf(dy * rsd, gg.y, bb.y), 0.0f);
    r.z = fmaxf(fmaf(dz * rsd, gg.z, bb.z), 0.0f);
    r.w = fmaxf(fmaf(dw * rsd, gg.w, bb.w), 0.0f);
    *reinterpret_cast<float4*>(out + (size_t)node * HID + lane * 4) = r;
}

// ---------------- column sum -------------------------------------------------
__global__ void colsum_kernel(const float* __restrict__ x, float* __restrict__ cs, int N) {
    int col = threadIdx.x & 127;
    int rg  = threadIdx.x >> 7;
    float s = 0.0f;
    for (int row = blockIdx.x * 2 + rg; row < N; row += gridDim.x * 2)
        s += x[(size_t)row * HID + col];
    atomicAdd(&cs[col], s);
}

// ---------------- output head ------------------------------------------------
__global__ void head_kernel(const float* __restrict__ cs,
                            const float* __restrict__ W1, const float* __restrict__ b1,
                            const float* __restrict__ W2, const float* __restrict__ b2,
                            float* __restrict__ out, float invN)
{
    __shared__ float g[HID], h[HID];
    int t = threadIdx.x;
    g[t] = cs[t] * invN;
    __syncthreads();
    float acc = b1[t];
#pragma unroll 8
    for (int k = 0; k < HID; ++k) acc = fmaf(g[k], W1[k * HID + t], acc);
    h[t] = fmaxf(acc, 0.0f);
    __syncthreads();
    float o = b2[t];
#pragma unroll 8
    for (int k = 0; k < HID; ++k) o = fmaf(h[k], W2[k * HID + t], o);
    out[t] = o;
}

// ---------------- launch ----------------------------------------------------
extern "C" void kernel_launch(void* const* d_in, const int* in_sizes, int n_in,
                              void* d_out, int out_size) {
    const float* node_feat = (const float*)d_in[0];
    const float* edge_attr = (const float*)d_in[1];
    const float* enc_W     = (const float*)d_in[2];
    const float* enc_b     = (const float*)d_in[3];
    const float* mlp_W1    = (const float*)d_in[4];
    const float* mlp_b1    = (const float*)d_in[5];
    const float* mlp_W2    = (const float*)d_in[6];
    const float* mlp_b2    = (const float*)d_in[7];
    const float* upd_W1    = (const float*)d_in[8];
    const float* upd_b1    = (const float*)d_in[9];
    const float* upd_W2    = (const float*)d_in[10];
    const float* upd_b2    = (const float*)d_in[11];
    const float* ln_g      = (const float*)d_in[12];
    const float* ln_b      = (const float*)d_in[13];
    const float* out_W1    = (const float*)d_in[14];
    const float* out_b1    = (const float*)d_in[15];
    const float* out_W2    = (const float*)d_in[16];
    const float* out_b2    = (const float*)d_in[17];
    const void*  edge_idx  = d_in[18];

    const int N = in_sizes[0] / 5;
    const int E = in_sizes[18] / 2;

    float *px, *pA, *pB, *pS, *pT, *pinv, *pmask, *pcs, *peas;
    int *pflag, *pcnt, *poff, *pcur, *pbsum, *psrcs;
    __nv_bfloat16 *pWh, *pWl;
    cudaGetSymbolAddress((void**)&px,    g_x);
    cudaGetSymbolAddress((void**)&pA,    g_A);
    cudaGetSymbolAddress((void**)&pB,    g_B);
    cudaGetSymbolAddress((void**)&pS,    g_S);
    cudaGetSymbolAddress((void**)&pT,    g_T);
    cudaGetSymbolAddress((void**)&pinv,  g_inv);
    cudaGetSymbolAddress((void**)&pmask, g_mask);
    cudaGetSymbolAddress((void**)&pcs,   g_colsum);
    cudaGetSymbolAddress((void**)&pflag, g_is64);
    cudaGetSymbolAddress((void**)&pcnt,  g_cnt);
    cudaGetSymbolAddress((void**)&poff,  g_off);
    cudaGetSymbolAddress((void**)&pcur,  g_cur);
    cudaGetSymbolAddress((void**)&pbsum, g_bsum);
    cudaGetSymbolAddress((void**)&psrcs, g_srcs);
    cudaGetSymbolAddress((void**)&peas,  g_eas);
    cudaGetSymbolAddress((void**)&pWh,   g_Wh);
    cudaGetSymbolAddress((void**)&pWl,   g_Wl);

    const int DSMEM = 4 * TILE_BYTES;   // 139264 bytes
    cudaFuncSetAttribute(mma_gemm, cudaFuncAttributeMaxDynamicSharedMemorySize, DSMEM);

    const int gemm_grid = (N + 127) / 128;
    const int scan_blocks = (N + 1023) / 1024;

    // --- CSR build (once; reused for all 3 layers) ---
    detect_idx_kernel<<<1, 1>>>(edge_idx, E, pflag);
    cudaMemsetAsync(pcnt, 0, (size_t)N * sizeof(int));
    hist_kernel<<<(E + 255) / 256, 256>>>(edge_idx, pflag, pcnt, E);
    scan1_kernel<<<scan_blocks, 1024>>>(pcnt, poff, pbsum, N);
    scan2_kernel<<<1, 32>>>(pbsum, scan_blocks);
    scan3_kernel<<<(N + 255) / 256, 256>>>(poff, pcur, pbsum, pcnt, pinv, pmask, N, E);
    scatter_kernel<<<(E + 255) / 256, 256>>>(edge_idx, pflag, edge_attr, pcur, psrcs, peas, E);

    encoder_kernel<<<(N * HID + 255) / 256, 256>>>(node_feat, enc_W, enc_b, px, N);
    prep_weights<<<18, 256>>>(mlp_W1, mlp_W2, upd_W1, upd_W2, pWh, pWl);

    for (int l = 0; l < 3; ++l) {
        const float* cve = mlp_W1 + (size_t)l * 257 * HID + 256 * HID; // edge_attr row
        const float* b1  = mlp_b1 + (size_t)l * HID;
        const float* b2  = mlp_b2 + (size_t)l * HID;
        const float* ub1 = upd_b1 + (size_t)l * HID;
        const float* ub2 = upd_b2 + (size_t)l * HID;
        __nv_bfloat16* W1a_h = pWh + (size_t)(l * 6 + 0) * 16384;
        __nv_bfloat16* W1a_l = pWl + (size_t)(l * 6 + 0) * 16384;
        __nv_bfloat16* W1b_h = pWh + (size_t)(l * 6 + 1) * 16384;
        __nv_bfloat16* W1b_l = pWl + (size_t)(l * 6 + 1) * 16384;
        __nv_bfloat16* W2_h  = pWh + (size_t)(l * 6 + 2) * 16384;
        __nv_bfloat16* W2_l  = pWl + (size_t)(l * 6 + 2) * 16384;
        __nv_bfloat16* U1a_h = pWh + (size_t)(l * 6 + 3) * 16384;
        __nv_bfloat16* U1a_l = pWl + (size_t)(l * 6 + 3) * 16384;
        __nv_bfloat16* U1b_h = pWh + (size_t)(l * 6 + 4) * 16384;
        __nv_bfloat16* U1b_l = pWl + (size_t)(l * 6 + 4) * 16384;
        __nv_bfloat16* U2_h  = pWh + (size_t)(l * 6 + 5) * 16384;
        __nv_bfloat16* U2_l  = pWl + (size_t)(l * 6 + 5) * 16384;

        // A_msg = x@W1a + b1 ; B_msg = x@W1b
        mma_gemm<<<gemm_grid, 256, DSMEM>>>(px, W1a_h, W1a_l, nullptr, nullptr, nullptr,
                                            b1, nullptr, nullptr, pA, N, 0);
        mma_gemm<<<gemm_grid, 256, DSMEM>>>(px, W1b_h, W1b_l, nullptr, nullptr, nullptr,
                                            nullptr, nullptr, nullptr, pB, N, 0);

        // S[i] = sum over CSR adj of relu(A[i]+B[src]+ea*c)   (no atomics)
        agg_kernel<<<(N * 32 + 255) / 256, 256>>>(pA, pB, psrcs, peas, poff, cve, pS, N);

        // aggr = (S*inv_deg)@W2 + b2*[deg>0]
        mma_gemm<<<gemm_grid, 256, DSMEM>>>(pS, W2_h, W2_l, nullptr, nullptr, nullptr,
                                            b2, pinv, pmask, pT, N, 0);

        // h = relu(x@U1a + aggr@U1b + ub1)
        mma_gemm<<<gemm_grid, 256, DSMEM>>>(px, U1a_h, U1a_l, pT, U1b_h, U1b_l,
                                            ub1, nullptr, nullptr, pA, N, 1);

        // x_new = h@U2 + ub2
        mma_gemm<<<gemm_grid, 256, DSMEM>>>(pA, U2_h, U2_l, nullptr, nullptr, nullptr,
                                            ub2, nullptr, nullptr, pB, N, 0);

        // x = relu(LN(x_new))
        ln_relu_kernel<<<(N * 32 + 255) / 256, 256>>>(pB, ln_g + (size_t)l * HID,
                                                      ln_b + (size_t)l * HID, px, N);
    }

    cudaMemsetAsync(pcs, 0, HID * sizeof(float));
    colsum_kernel<<<128, 256>>>(px, pcs, N);
    head_kernel<<<1, HID>>>(pcs, out_W1, out_b1, out_W2, out_b2,
                            (float*)d_out, 1.0f / (float)N);
}

// round 6
// speedup vs baseline: 2.4472x; 1.1319x over previous
#include <cuda_runtime.h>
#include <cuda_bf16.h>
#include <cstdint>

#define NNODES 50000
#define NEDGES 800000
#define HID    128

// ---------------- scratch (device globals; no allocation allowed) ----------
__device__ float g_x[NNODES * HID];
__device__ float g_A[NNODES * HID];
__device__ float g_B[NNODES * HID];
__device__ float g_S[NNODES * HID];
__device__ float g_T[NNODES * HID];
__device__ float g_inv[NNODES];
__device__ float g_mask[NNODES];
__device__ float g_colsum[HID];
__device__ int   g_is64;
// CSR by dst
__device__ int   g_cnt[NNODES];
__device__ int   g_off[NNODES + 1];
__device__ int   g_cur[NNODES];
__device__ int   g_bsum[64];
__device__ int   g_srcs[NEDGES];
__device__ float g_eas[NEDGES];
// 18 weight slices (3 layers x {W1a,W1b,W2,U1a,U1b,U2}), each 128x128 bf16,
// transposed ([out][k], packed row-major), hi and lo parts.
__device__ __nv_bfloat16 g_Wh[18 * 16384];
__device__ __nv_bfloat16 g_Wl[18 * 16384];

// ---------------- helpers ----------------------------------------------------
__device__ __forceinline__ uint32_t smem_to_u32(const void* smem_ptr) {
    uint32_t addr;
    asm("{ .reg .u64 tmp; cvta.to.shared.u64 tmp, %1; cvt.u32.u64 %0, tmp; }"
        : "=r"(addr) : "l"(smem_ptr));
    return addr;
}
__device__ __forceinline__ uint32_t split_pair(float a, float b, uint32_t& lo) {
    __nv_bfloat16 ha = __float2bfloat16(a), hb = __float2bfloat16(b);
    __nv_bfloat16 la = __float2bfloat16(a - __bfloat162float(ha));
    __nv_bfloat16 lb = __float2bfloat16(b - __bfloat162float(hb));
    lo = (uint32_t)__bfloat16_as_ushort(la) | ((uint32_t)__bfloat16_as_ushort(lb) << 16);
    return (uint32_t)__bfloat16_as_ushort(ha) | ((uint32_t)__bfloat16_as_ushort(hb) << 16);
}
__device__ __forceinline__ void ldmatrix_x4(uint32_t& r0, uint32_t& r1,
                                            uint32_t& r2, uint32_t& r3, uint32_t addr) {
    asm volatile("ldmatrix.sync.aligned.m8n8.x4.shared.b16 {%0,%1,%2,%3}, [%4];"
                 : "=r"(r0), "=r"(r1), "=r"(r2), "=r"(r3) : "r"(addr));
}
__device__ __forceinline__ void mma16816(float* d, const uint32_t* a, const uint32_t* b) {
    asm volatile(
        "mma.sync.aligned.m16n8k16.row.col.f32.bf16.bf16.f32 "
        "{%0,%1,%2,%3}, {%4,%5,%6,%7}, {%8,%9}, {%0,%1,%2,%3};"
        : "+f"(d[0]), "+f"(d[1]), "+f"(d[2]), "+f"(d[3])
        : "r"(a[0]), "r"(a[1]), "r"(a[2]), "r"(a[3]), "r"(b[0]), "r"(b[1]));
}

#define ROWB 272
#define TILE_BYTES (128 * ROWB)   // 34816
#define DSMEM_SZ (4 * TILE_BYTES) // 139264
#define STAGE_STRIDE 132          // fp32 staging row stride (words)

// ---- common fill helpers (device inline) -----------------------------------
__device__ __forceinline__ void fill_B_tiles(char* Bh, char* Bl,
                                             const uint4* gBh, const uint4* gBl, int tid) {
#pragma unroll
    for (int i = 0; i < 8; ++i) {
        int cidx = tid + i * 256;
        int row = cidx >> 4, c = cidx & 15;
        uint32_t off = (uint32_t)(row * ROWB + c * 16);
        *reinterpret_cast<uint4*>(Bh + off) = gBh[cidx];
        *reinterpret_cast<uint4*>(Bl + off) = gBl[cidx];
    }
}
__device__ __forceinline__ void fill_A_tiles(char* Ah, char* Al, const float* A,
                                             const float* rowscale, int m0, int M, int tid) {
#pragma unroll
    for (int i = 0; i < 8; ++i) {
        int cidx = tid + i * 256;
        int row = cidx >> 4, c = cidx & 15;
        int arow = m0 + row;
        int k0 = c * 8;
        uint32_t off = (uint32_t)(row * ROWB + c * 16);
        uint4 hv4 = make_uint4(0u, 0u, 0u, 0u), lv4 = make_uint4(0u, 0u, 0u, 0u);
        if (arow < M) {
            float4 v0 = *reinterpret_cast<const float4*>(A + (size_t)arow * HID + k0);
            float4 v1 = *reinterpret_cast<const float4*>(A + (size_t)arow * HID + k0 + 4);
            if (rowscale != nullptr) {
                float rs = rowscale[arow];
                v0.x *= rs; v0.y *= rs; v0.z *= rs; v0.w *= rs;
                v1.x *= rs; v1.y *= rs; v1.z *= rs; v1.w *= rs;
            }
            uint32_t lo;
            hv4.x = split_pair(v0.x, v0.y, lo); lv4.x = lo;
            hv4.y = split_pair(v0.z, v0.w, lo); lv4.y = lo;
            hv4.z = split_pair(v1.x, v1.y, lo); lv4.z = lo;
            hv4.w = split_pair(v1.z, v1.w, lo); lv4.w = lo;
        }
        *reinterpret_cast<uint4*>(Ah + off) = hv4;
        *reinterpret_cast<uint4*>(Al + off) = lv4;
    }
}
// 3-pass split MMA over current smem tiles into acc
__device__ __forceinline__ void mma_3pass(float acc[2][8][4],
                                          uint32_t sAh, uint32_t sAl,
                                          uint32_t sBh, uint32_t sBl,
                                          const uint32_t a_off[2], const uint32_t b_off[4]) {
    uint32_t pa[3] = { sAh, sAl, sAh };
    uint32_t pb[3] = { sBh, sBh, sBl };
#pragma unroll
    for (int p = 0; p < 3; ++p) {
        uint32_t abase = pa[p], bbase = pb[p];
#pragma unroll
        for (int kk = 0; kk < 8; ++kk) {
            uint32_t a[2][4];
            uint32_t b[8][2];
#pragma unroll
            for (int mt = 0; mt < 2; ++mt)
                ldmatrix_x4(a[mt][0], a[mt][1], a[mt][2], a[mt][3],
                            abase + a_off[mt] + kk * 32);
#pragma unroll
            for (int bt = 0; bt < 4; ++bt)
                ldmatrix_x4(b[2 * bt][0], b[2 * bt][1], b[2 * bt + 1][0], b[2 * bt + 1][1],
                            bbase + b_off[bt] + kk * 32);
#pragma unroll
            for (int mt = 0; mt < 2; ++mt)
#pragma unroll
                for (int nt = 0; nt < 8; ++nt)
                    mma16816(acc[mt][nt], a[mt], b[nt]);
        }
    }
}

// ---------------- index dtype detection ------------------------------------
__global__ void detect_idx_kernel(const void* idx, int E, int* flag) {
    const long long* p = (const long long*)idx;
    int is64 = 1;
    int n = (E < 128) ? E : 128;
    for (int i = 0; i < n; ++i) {
        long long v = p[i];
        if (v < 0 || v >= NNODES) { is64 = 0; break; }
    }
    *flag = is64;
}
__device__ __forceinline__ int load_idx(const void* idx, int is64, long long pos) {
    if (is64) return (int)((const long long*)idx)[pos];
    return ((const int*)idx)[pos];
}

// ---------------- CSR build --------------------------------------------------
__global__ void hist_kernel(const void* __restrict__ idx, const int* __restrict__ flag,
                            int* __restrict__ cnt, int E) {
    int e = blockIdx.x * blockDim.x + threadIdx.x;
    if (e >= E) return;
    int dst = load_idx(idx, *flag, (long long)E + e);
    atomicAdd(&cnt[dst], 1);
}
__global__ void scan1_kernel(const int* __restrict__ cnt, int* __restrict__ off,
                             int* __restrict__ bsum, int N) {
    __shared__ int sm[1024];
    int i = blockIdx.x * 1024 + threadIdx.x;
    int v = (i < N) ? cnt[i] : 0;
    sm[threadIdx.x] = v;
    __syncthreads();
#pragma unroll
    for (int o = 1; o < 1024; o <<= 1) {
        int t = (threadIdx.x >= o) ? sm[threadIdx.x - o] : 0;
        __syncthreads();
        sm[threadIdx.x] += t;
        __syncthreads();
    }
    if (i < N) off[i] = sm[threadIdx.x] - v;   // exclusive
    if (threadIdx.x == 1023) bsum[blockIdx.x] = sm[1023];
}
__global__ void scan2_kernel(int* bsum, int nb) {
    __shared__ int sm[64];
    int t = threadIdx.x;
    int v = (t < nb) ? bsum[t] : 0;
    sm[t] = v;
    __syncthreads();
#pragma unroll
    for (int o = 1; o < 64; o <<= 1) {
        int u = (t >= o) ? sm[t - o] : 0;
        __syncthreads();
        sm[t] += u;
        __syncthreads();
    }
    if (t < nb) bsum[t] = sm[t] - v;   // exclusive
}
__global__ void scan3_kernel(int* __restrict__ off, int* __restrict__ cur,
                             const int* __restrict__ bsum,
                             const int* __restrict__ cnt,
                             float* __restrict__ inv, float* __restrict__ mask,
                             int N, int E) {
    int i = blockIdx.x * blockDim.x + threadIdx.x;
    if (i == 0) off[N] = E;
    if (i >= N) return;
    int o = off[i] + bsum[i >> 10];
    off[i] = o;
    cur[i] = o;
    int c = cnt[i];
    inv[i]  = 1.0f / (float)((c > 1) ? c : 1);
    mask[i] = (c > 0) ? 1.0f : 0.0f;
}
__global__ void scatter_kernel(const void* __restrict__ idx, const int* __restrict__ flag,
                               const float* __restrict__ eattr,
                               int* __restrict__ cur, int* __restrict__ srcs,
                               float* __restrict__ eas, int E) {
    int e = blockIdx.x * blockDim.x + threadIdx.x;
    if (e >= E) return;
    int is64 = *flag;
    int src = load_idx(idx, is64, e);
    int dst = load_idx(idx, is64, (long long)E + e);
    int p = atomicAdd(&cur[dst], 1);
    srcs[p] = src;
    eas[p]  = eattr[e];
}

// ---------------- encoder ----------------------------------------------------
__global__ void encoder_kernel(const float* __restrict__ nf, const float* __restrict__ W,
                               const float* __restrict__ b, float* __restrict__ x, int N) {
    int i = blockIdx.x * blockDim.x + threadIdx.x;
    if (i >= N * HID) return;
    int n = i >> 7;
    int h = i & 127;
    float acc = b[h];
#pragma unroll
    for (int k = 0; k < 5; ++k)
        acc = fmaf(nf[n * 5 + k], W[k * HID + h], acc);
    x[i] = acc;
}

// ---------------- weight prep ------------------------------------------------
__global__ void prep_weights(const float* __restrict__ mlp_W1, const float* __restrict__ mlp_W2,
                             const float* __restrict__ upd_W1, const float* __restrict__ upd_W2,
                             __nv_bfloat16* __restrict__ Wh, __nv_bfloat16* __restrict__ Wl) {
    int s = blockIdx.x;            // 0..17
    int l = s / 6, j = s % 6;
    const float* src;
    switch (j) {
        case 0:  src = mlp_W1 + (size_t)l * 257 * 128; break;
        case 1:  src = mlp_W1 + (size_t)l * 257 * 128 + 128 * 128; break;
        case 2:  src = mlp_W2 + (size_t)l * 128 * 128; break;
        case 3:  src = upd_W1 + (size_t)l * 256 * 128; break;
        case 4:  src = upd_W1 + (size_t)l * 256 * 128 + 128 * 128; break;
        default: src = upd_W2 + (size_t)l * 128 * 128; break;
    }
    uint4* dh = reinterpret_cast<uint4*>(Wh + (size_t)s * 16384);
    uint4* dl = reinterpret_cast<uint4*>(Wl + (size_t)s * 16384);
    for (int c = threadIdx.x; c < 2048; c += blockDim.x) {
        int out = c >> 4, k0 = (c & 15) * 8;
        uint32_t hv[4], lv[4];
#pragma unroll
        for (int u = 0; u < 4; ++u) {
            float a = src[(size_t)(k0 + 2 * u) * 128 + out];
            float b = src[(size_t)(k0 + 2 * u + 1) * 128 + out];
            hv[u] = split_pair(a, b, lv[u]);
        }
        dh[c] = make_uint4(hv[0], hv[1], hv[2], hv[3]);
        dl[c] = make_uint4(lv[0], lv[1], lv[2], lv[3]);
    }
}

// ---------------- generic single-slice GEMM (for S@W2) -----------------------
__global__ __launch_bounds__(256) void mma_gemm(
    const float* __restrict__ A0,
    const __nv_bfloat16* __restrict__ B0h, const __nv_bfloat16* __restrict__ B0l,
    const float* __restrict__ bias, const float* __restrict__ rowscale,
    const float* __restrict__ biasmask,
    float* __restrict__ C, int M)
{
    extern __shared__ char sm[];
    char* Ah = sm;
    char* Al = sm + TILE_BYTES;
    char* Bh = sm + 2 * TILE_BYTES;
    char* Bl = sm + 3 * TILE_BYTES;
    const uint32_t sAh = smem_to_u32(Ah), sAl = smem_to_u32(Al);
    const uint32_t sBh = smem_to_u32(Bh), sBl = smem_to_u32(Bl);

    const int tid  = threadIdx.x;
    const int wid  = tid >> 5;
    const int lane = tid & 31;
    const int warp_m = wid & 3;
    const int warp_n = wid >> 2;
    const int m0 = blockIdx.x * 128;

    float acc[2][8][4];
#pragma unroll
    for (int i = 0; i < 2; ++i)
#pragma unroll
        for (int j = 0; j < 8; ++j)
#pragma unroll
            for (int k = 0; k < 4; ++k) acc[i][j][k] = 0.0f;

    uint32_t a_off[2], b_off[4];
#pragma unroll
    for (int mt = 0; mt < 2; ++mt)
        a_off[mt] = (uint32_t)((warp_m * 32 + mt * 16 + (lane & 15)) * ROWB + (lane >> 4) * 16);
#pragma unroll
    for (int bt = 0; bt < 4; ++bt)
        b_off[bt] = (uint32_t)((warp_n * 64 + bt * 16 + ((lane >> 4) & 1) * 8 + (lane & 7)) * ROWB
                               + ((lane >> 3) & 1) * 16);

    fill_B_tiles(Bh, Bl, reinterpret_cast<const uint4*>(B0h),
                 reinterpret_cast<const uint4*>(B0l), tid);
    fill_A_tiles(Ah, Al, A0, rowscale, m0, M, tid);
    __syncthreads();
    mma_3pass(acc, sAh, sAl, sBh, sBl, a_off, b_off);

#pragma unroll
    for (int mt = 0; mt < 2; ++mt) {
        int r0 = m0 + warp_m * 32 + mt * 16 + (lane >> 2);
#pragma unroll
        for (int half = 0; half < 2; ++half) {
            int r = r0 + half * 8;
            if (r >= M) continue;
            float bm = (biasmask != nullptr) ? biasmask[r] : 1.0f;
#pragma unroll
            for (int nt = 0; nt < 8; ++nt) {
                int col = warp_n * 64 + nt * 8 + (lane & 3) * 2;
                float v0 = acc[mt][nt][2 * half + 0];
                float v1 = acc[mt][nt][2 * half + 1];
                if (bias != nullptr) {
                    v0 = fmaf(bm, bias[col + 0], v0);
                    v1 = fmaf(bm, bias[col + 1], v1);
                }
                *reinterpret_cast<float2*>(C + (size_t)r * HID + col) = make_float2(v0, v1);
            }
        }
    }
}

// ---------------- fused message-pair GEMM: C0=x@W1a+b1, C1=x@W1b -------------
__global__ __launch_bounds__(256) void mma_gemm_msg(
    const float* __restrict__ X,
    const __nv_bfloat16* __restrict__ B0h, const __nv_bfloat16* __restrict__ B0l,
    const __nv_bfloat16* __restrict__ B1h, const __nv_bfloat16* __restrict__ B1l,
    const float* __restrict__ bias0,
    float* __restrict__ C0, float* __restrict__ C1, int M)
{
    extern __shared__ char sm[];
    char* Ah = sm;
    char* Al = sm + TILE_BYTES;
    char* Bh = sm + 2 * TILE_BYTES;
    char* Bl = sm + 3 * TILE_BYTES;
    const uint32_t sAh = smem_to_u32(Ah), sAl = smem_to_u32(Al);
    const uint32_t sBh = smem_to_u32(Bh), sBl = smem_to_u32(Bl);

    const int tid  = threadIdx.x;
    const int wid  = tid >> 5;
    const int lane = tid & 31;
    const int warp_m = wid & 3;
    const int warp_n = wid >> 2;
    const int m0 = blockIdx.x * 128;

    uint32_t a_off[2], b_off[4];
#pragma unroll
    for (int mt = 0; mt < 2; ++mt)
        a_off[mt] = (uint32_t)((warp_m * 32 + mt * 16 + (lane & 15)) * ROWB + (lane >> 4) * 16);
#pragma unroll
    for (int bt = 0; bt < 4; ++bt)
        b_off[bt] = (uint32_t)((warp_n * 64 + bt * 16 + ((lane >> 4) & 1) * 8 + (lane & 7)) * ROWB
                               + ((lane >> 3) & 1) * 16);

    fill_A_tiles(Ah, Al, X, nullptr, m0, M, tid);

#pragma unroll 1
    for (int j = 0; j < 2; ++j) {
        if (j) __syncthreads();   // previous MMA reads done before B refill
        fill_B_tiles(Bh, Bl,
                     reinterpret_cast<const uint4*>(j ? B1h : B0h),
                     reinterpret_cast<const uint4*>(j ? B1l : B0l), tid);
        __syncthreads();

        float acc[2][8][4];
#pragma unroll
        for (int a = 0; a < 2; ++a)
#pragma unroll
            for (int b = 0; b < 8; ++b)
#pragma unroll
                for (int c = 0; c < 4; ++c) acc[a][b][c] = 0.0f;
        mma_3pass(acc, sAh, sAl, sBh, sBl, a_off, b_off);

        float* C = j ? C1 : C0;
        const float* bias = j ? nullptr : bias0;
#pragma unroll
        for (int mt = 0; mt < 2; ++mt) {
            int r0 = m0 + warp_m * 32 + mt * 16 + (lane >> 2);
#pragma unroll
            for (int half = 0; half < 2; ++half) {
                int r = r0 + half * 8;
                if (r >= M) continue;
#pragma unroll
                for (int nt = 0; nt < 8; ++nt) {
                    int col = warp_n * 64 + nt * 8 + (lane & 3) * 2;
                    float v0 = acc[mt][nt][2 * half + 0];
                    float v1 = acc[mt][nt][2 * half + 1];
                    if (bias != nullptr) { v0 += bias[col]; v1 += bias[col + 1]; }
                    *reinterpret_cast<float2*>(C + (size_t)r * HID + col) = make_float2(v0, v1);
                }
            }
        }
    }
}

// ---------------- fused update layer -----------------------------------------
// h = relu(X@U1a + T@U1b + ub1); x_new = h@U2 + ub2; X_out = relu(LN(x_new))
__global__ __launch_bounds__(256) void update_fused(
    const float* __restrict__ X,
    const __nv_bfloat16* __restrict__ U1ah, const __nv_bfloat16* __restrict__ U1al,
    const float* __restrict__ T,
    const __nv_bfloat16* __restrict__ U1bh, const __nv_bfloat16* __restrict__ U1bl,
    const float* __restrict__ ub1,
    const __nv_bfloat16* __restrict__ U2h, const __nv_bfloat16* __restrict__ U2l,
    const float* __restrict__ ub2,
    const float* __restrict__ lng, const float* __restrict__ lnb,
    float* __restrict__ Xout, int M)
{
    extern __shared__ char sm[];
    char* Ah = sm;
    char* Al = sm + TILE_BYTES;
    char* Bh = sm + 2 * TILE_BYTES;
    char* Bl = sm + 3 * TILE_BYTES;
    float* stage = reinterpret_cast<float*>(Bh);   // reused AFTER stage-2 MMA
    const uint32_t sAh = smem_to_u32(Ah), sAl = smem_to_u32(Al);
    const uint32_t sBh = smem_to_u32(Bh), sBl = smem_to_u32(Bl);

    const int tid  = threadIdx.x;
    const int wid  = tid >> 5;
    const int lane = tid & 31;
    const int warp_m = wid & 3;
    const int warp_n = wid >> 2;
    const int m0 = blockIdx.x * 128;

    uint32_t a_off[2], b_off[4];
#pragma unroll
    for (int mt = 0; mt < 2; ++mt)
        a_off[mt] = (uint32_t)((warp_m * 32 + mt * 16 + (lane & 15)) * ROWB + (lane >> 4) * 16);
#pragma unroll
    for (int bt = 0; bt < 4; ++bt)
        b_off[bt] = (uint32_t)((warp_n * 64 + bt * 16 + ((lane >> 4) & 1) * 8 + (lane & 7)) * ROWB
                               + ((lane >> 3) & 1) * 16);

    // ---- stage 1: acc = X@U1a + T@U1b ----
    float acc[2][8][4];
#pragma unroll
    for (int a = 0; a < 2; ++a)
#pragma unroll
        for (int b = 0; b < 8; ++b)
#pragma unroll
            for (int c = 0; c < 4; ++c) acc[a][b][c] = 0.0f;

#pragma unroll 1
    for (int s = 0; s < 2; ++s) {
        if (s) __syncthreads();
        fill_A_tiles(Ah, Al, s ? T : X, nullptr, m0, M, tid);
        fill_B_tiles(Bh, Bl,
                     reinterpret_cast<const uint4*>(s ? U1bh : U1ah),
                     reinterpret_cast<const uint4*>(s ? U1bl : U1al), tid);
        __syncthreads();
        mma_3pass(acc, sAh, sAl, sBh, sBl, a_off, b_off);
    }

    // ---- h = relu(acc + ub1) -> write split bf16 back into A tiles ----
    __syncthreads();   // all warps done reading A tiles
#pragma unroll
    for (int mt = 0; mt < 2; ++mt) {
#pragma unroll
        for (int half = 0; half < 2; ++half) {
            int lr = warp_m * 32 + mt * 16 + (lane >> 2) + half * 8;
#pragma unroll
            for (int nt = 0; nt < 8; ++nt) {
                int col = warp_n * 64 + nt * 8 + (lane & 3) * 2;
                float v0 = fmaxf(acc[mt][nt][2 * half + 0] + ub1[col + 0], 0.0f);
                float v1 = fmaxf(acc[mt][nt][2 * half + 1] + ub1[col + 1], 0.0f);
                uint32_t lo;
                uint32_t hi = split_pair(v0, v1, lo);
                uint32_t off = (uint32_t)(lr * ROWB + col * 2);
                *reinterpret_cast<uint32_t*>(Ah + off) = hi;
                *reinterpret_cast<uint32_t*>(Al + off) = lo;
            }
        }
    }
    // ---- stage 2: x_new = h@U2 ----
    fill_B_tiles(Bh, Bl, reinterpret_cast<const uint4*>(U2h),
                 reinterpret_cast<const uint4*>(U2l), tid);
    __syncthreads();
#pragma unroll
    for (int a = 0; a < 2; ++a)
#pragma unroll
        for (int b = 0; b < 8; ++b)
#pragma unroll
            for (int c = 0; c < 4; ++c) acc[a][b][c] = 0.0f;
    mma_3pass(acc, sAh, sAl, sBh, sBl, a_off, b_off);

    // ---- epilogue: + ub2, stage fp32 rows into smem ----
    __syncthreads();   // all warps done reading B tiles (stage aliases Bh)
#pragma unroll
    for (int mt = 0; mt < 2; ++mt) {
#pragma unroll
        for (int half = 0; half < 2; ++half) {
            int lr = warp_m * 32 + mt * 16 + (lane >> 2) + half * 8;
#pragma unroll
            for (int nt = 0; nt < 8; ++nt) {
                int col = warp_n * 64 + nt * 8 + (lane & 3) * 2;
                float v0 = acc[mt][nt][2 * half + 0] + ub2[col + 0];
                float v1 = acc[mt][nt][2 * half + 1] + ub2[col + 1];
                *reinterpret_cast<float2*>(stage + lr * STAGE_STRIDE + col) =
                    make_float2(v0, v1);
            }
        }
    }
    __syncthreads();

    // ---- LN + relu from staging, write Xout ----
#pragma unroll 1
    for (int i = 0; i < 16; ++i) {
        int lr = wid * 16 + i;
        int r = m0 + lr;
        if (r >= M) break;
        float4 v = *reinterpret_cast<const float4*>(stage + lr * STAGE_STRIDE + lane * 4);
        float s = v.x + v.y + v.z + v.w;
#pragma unroll
        for (int o = 16; o > 0; o >>= 1) s += __shfl_xor_sync(0xffffffffu, s, o);
        float mu = s * (1.0f / 128.0f);
        float dx = v.x - mu, dy = v.y - mu, dz = v.z - mu, dw = v.w - mu;
        float q = dx * dx + dy * dy + dz * dz + dw * dw;
#pragma unroll
        for (int o = 16; o > 0; o >>= 1) q += __shfl_xor_sync(0xffffffffu, q, o);
        float rsd = rsqrtf(q * (1.0f / 128.0f) + 1e-5f);
        float4 gg = *reinterpret_cast<const float4*>(lng + lane * 4);
        float4 bb = *reinterpret_cast<const float4*>(lnb + lane * 4);
        float4 rr;
        rr.x = fmaxf(fmaf(dx * rsd, gg.x, bb.x), 0.0f);
        rr.y = fmaxf(fmaf(dy * rsd, gg.y, bb.y), 0.0f);
        rr.z = fmaxf(fmaf(dz * rsd, gg.z, bb.z), 0.0f);
        rr.w = fmaxf(fmaf(dw * rsd, gg.w, bb.w), 0.0f);
        *reinterpret_cast<float4*>(Xout + (size_t)r * HID + lane * 4) = rr;
    }
}

// ---------------- CSR aggregation --------------------------------------------
__global__ __launch_bounds__(256) void agg_kernel(
    const float* __restrict__ A, const float* __restrict__ B,
    const int* __restrict__ srcs, const float* __restrict__ eas,
    const int* __restrict__ off, const float* __restrict__ cvec,
    float* __restrict__ S, int N)
{
    int node = (blockIdx.x * blockDim.x + threadIdx.x) >> 5;
    if (node >= N) return;
    int lane = threadIdx.x & 31;
    const float4 a = *reinterpret_cast<const float4*>(A + (size_t)node * HID + lane * 4);
    const float4 c = *reinterpret_cast<const float4*>(cvec + lane * 4);
    float4 s = make_float4(0.f, 0.f, 0.f, 0.f);
    int p  = off[node];
    int pe = off[node + 1];
    for (; p + 1 < pe; p += 2) {
        int s0 = srcs[p], s1 = srcs[p + 1];
        float e0 = eas[p], e1 = eas[p + 1];
        const float4 b0 = *reinterpret_cast<const float4*>(B + (size_t)s0 * HID + lane * 4);
        const float4 b1 = *reinterpret_cast<const float4*>(B + (size_t)s1 * HID + lane * 4);
        s.x += fmaxf(fmaf(e0, c.x, a.x + b0.x), 0.0f) + fmaxf(fmaf(e1, c.x, a.x + b1.x), 0.0f);
        s.y += fmaxf(fmaf(e0, c.y, a.y + b0.y), 0.0f) + fmaxf(fmaf(e1, c.y, a.y + b1.y), 0.0f);
        s.z += fmaxf(fmaf(e0, c.z, a.z + b0.z), 0.0f) + fmaxf(fmaf(e1, c.z, a.z + b1.z), 0.0f);
        s.w += fmaxf(fmaf(e0, c.w, a.w + b0.w), 0.0f) + fmaxf(fmaf(e1, c.w, a.w + b1.w), 0.0f);
    }
    if (p < pe) {
        int s0 = srcs[p];
        float e0 = eas[p];
        const float4 b0 = *reinterpret_cast<const float4*>(B + (size_t)s0 * HID + lane * 4);
        s.x += fmaxf(fmaf(e0, c.x, a.x + b0.x), 0.0f);
        s.y += fmaxf(fmaf(e0, c.y, a.y + b0.y), 0.0f);
        s.z += fmaxf(fmaf(e0, c.z, a.z + b0.z), 0.0f);
        s.w += fmaxf(fmaf(e0, c.w, a.w + b0.w), 0.0f);
    }
    *reinterpret_cast<float4*>(S + (size_t)node * HID + lane * 4) = s;
}

// ---------------- column sum + head ------------------------------------------
__global__ void colsum_kernel(const float* __restrict__ x, float* __restrict__ cs, int N) {
    int col = threadIdx.x & 127;
    int rg  = threadIdx.x >> 7;
    float s = 0.0f;
    for (int row = blockIdx.x * 2 + rg; row < N; row += gridDim.x * 2)
        s += x[(size_t)row * HID + col];
    atomicAdd(&cs[col], s);
}
__global__ void head_kernel(const float* __restrict__ cs,
                            const float* __restrict__ W1, const float* __restrict__ b1,
                            const float* __restrict__ W2, const float* __restrict__ b2,
                            float* __restrict__ out, float invN)
{
    __shared__ float g[HID], h[HID];
    int t = threadIdx.x;
    g[t] = cs[t] * invN;
    __syncthreads();
    float acc = b1[t];
#pragma unroll 8
    for (int k = 0; k < HID; ++k) acc = fmaf(g[k], W1[k * HID + t], acc);
    h[t] = fmaxf(acc, 0.0f);
    __syncthreads();
    float o = b2[t];
#pragma unroll 8
    for (int k = 0; k < HID; ++k) o = fmaf(h[k], W2[k * HID + t], o);
    out[t] = o;
}

// ---------------- launch ----------------------------------------------------
extern "C" void kernel_launch(void* const* d_in, const int* in_sizes, int n_in,
                              void* d_out, int out_size) {
    const float* node_feat = (const float*)d_in[0];
    const float* edge_attr = (const float*)d_in[1];
    const float* enc_W     = (const float*)d_in[2];
    const float* enc_b     = (const float*)d_in[3];
    const float* mlp_W1    = (const float*)d_in[4];
    const float* mlp_b1    = (const float*)d_in[5];
    const float* mlp_W2    = (const float*)d_in[6];
    const float* mlp_b2    = (const float*)d_in[7];
    const float* upd_W1    = (const float*)d_in[8];
    const float* upd_b1    = (const float*)d_in[9];
    const float* upd_W2    = (const float*)d_in[10];
    const float* upd_b2    = (const float*)d_in[11];
    const float* ln_g      = (const float*)d_in[12];
    const float* ln_b      = (const float*)d_in[13];
    const float* out_W1    = (const float*)d_in[14];
    const float* out_b1    = (const float*)d_in[15];
    const float* out_W2    = (const float*)d_in[16];
    const float* out_b2    = (const float*)d_in[17];
    const void*  edge_idx  = d_in[18];

    const int N = in_sizes[0] / 5;
    const int E = in_sizes[18] / 2;

    float *px, *pA, *pB, *pS, *pT, *pinv, *pmask, *pcs, *peas;
    int *pflag, *pcnt, *poff, *pcur, *pbsum, *psrcs;
    __nv_bfloat16 *pWh, *pWl;
    cudaGetSymbolAddress((void**)&px,    g_x);
    cudaGetSymbolAddress((void**)&pA,    g_A);
    cudaGetSymbolAddress((void**)&pB,    g_B);
    cudaGetSymbolAddress((void**)&pS,    g_S);
    cudaGetSymbolAddress((void**)&pT,    g_T);
    cudaGetSymbolAddress((void**)&pinv,  g_inv);
    cudaGetSymbolAddress((void**)&pmask, g_mask);
    cudaGetSymbolAddress((void**)&pcs,   g_colsum);
    cudaGetSymbolAddress((void**)&pflag, g_is64);
    cudaGetSymbolAddress((void**)&pcnt,  g_cnt);
    cudaGetSymbolAddress((void**)&poff,  g_off);
    cudaGetSymbolAddress((void**)&pcur,  g_cur);
    cudaGetSymbolAddress((void**)&pbsum, g_bsum);
    cudaGetSymbolAddress((void**)&psrcs, g_srcs);
    cudaGetSymbolAddress((void**)&peas,  g_eas);
    cudaGetSymbolAddress((void**)&pWh,   g_Wh);
    cudaGetSymbolAddress((void**)&pWl,   g_Wl);

    cudaFuncSetAttribute(mma_gemm, cudaFuncAttributeMaxDynamicSharedMemorySize, DSMEM_SZ);
    cudaFuncSetAttribute(mma_gemm_msg, cudaFuncAttributeMaxDynamicSharedMemorySize, DSMEM_SZ);
    cudaFuncSetAttribute(update_fused, cudaFuncAttributeMaxDynamicSharedMemorySize, DSMEM_SZ);

    const int gemm_grid = (N + 127) / 128;
    const int scan_blocks = (N + 1023) / 1024;

    // --- CSR build (once; reused for all 3 layers) ---
    detect_idx_kernel<<<1, 1>>>(edge_idx, E, pflag);
    cudaMemsetAsync(pcnt, 0, (size_t)N * sizeof(int));
    hist_kernel<<<(E + 255) / 256, 256>>>(edge_idx, pflag, pcnt, E);
    scan1_kernel<<<scan_blocks, 1024>>>(pcnt, poff, pbsum, N);
    scan2_kernel<<<1, 64>>>(pbsum, scan_blocks);
    scan3_kernel<<<(N + 255) / 256, 256>>>(poff, pcur, pbsum, pcnt, pinv, pmask, N, E);
    scatter_kernel<<<(E + 255) / 256, 256>>>(edge_idx, pflag, edge_attr, pcur, psrcs, peas, E);

    encoder_kernel<<<(N * HID + 255) / 256, 256>>>(node_feat, enc_W, enc_b, px, N);
    prep_weights<<<18, 256>>>(mlp_W1, mlp_W2, upd_W1, upd_W2, pWh, pWl);

    for (int l = 0; l < 3; ++l) {
        const float* cve = mlp_W1 + (size_t)l * 257 * HID + 256 * HID; // edge_attr row
        const float* b1  = mlp_b1 + (size_t)l * HID;
        const float* b2  = mlp_b2 + (size_t)l * HID;
        const float* ub1 = upd_b1 + (size_t)l * HID;
        const float* ub2 = upd_b2 + (size_t)l * HID;
        __nv_bfloat16* W1a_h = pWh + (size_t)(l * 6 + 0) * 16384;
        __nv_bfloat16* W1a_l = pWl + (size_t)(l * 6 + 0) * 16384;
        __nv_bfloat16* W1b_h = pWh + (size_t)(l * 6 + 1) * 16384;
        __nv_bfloat16* W1b_l = pWl + (size_t)(l * 6 + 1) * 16384;
        __nv_bfloat16* W2_h  = pWh + (size_t)(l * 6 + 2) * 16384;
        __nv_bfloat16* W2_l  = pWl + (size_t)(l * 6 + 2) * 16384;
        __nv_bfloat16* U1a_h = pWh + (size_t)(l * 6 + 3) * 16384;
        __nv_bfloat16* U1a_l = pWl + (size_t)(l * 6 + 3) * 16384;
        __nv_bfloat16* U1b_h = pWh + (size_t)(l * 6 + 4) * 16384;
        __nv_bfloat16* U1b_l = pWl + (size_t)(l * 6 + 4) * 16384;
        __nv_bfloat16* U2_h  = pWh + (size_t)(l * 6 + 5) * 16384;
        __nv_bfloat16* U2_l  = pWl + (size_t)(l * 6 + 5) * 16384;

        // A_msg = x@W1a + b1 ; B_msg = x@W1b   (one fused kernel)
        mma_gemm_msg<<<gemm_grid, 256, DSMEM_SZ>>>(px, W1a_h, W1a_l, W1b_h, W1b_l,
                                                   b1, pA, pB, N);

        // S[i] = sum over CSR adj of relu(A[i]+B[src]+ea*c)
        agg_kernel<<<(N * 32 + 255) / 256, 256>>>(pA, pB, psrcs, peas, poff, cve, pS, N);

        // aggr = (S*inv_deg)@W2 + b2*[deg>0]
        mma_gemm<<<gemm_grid, 256, DSMEM_SZ>>>(pS, W2_h, W2_l, b2, pinv, pmask, pT, N);

        // x = relu(LN(relu(x@U1a + aggr@U1b + ub1)@U2 + ub2))  (one fused kernel)
        update_fused<<<gemm_grid, 256, DSMEM_SZ>>>(px, U1a_h, U1a_l, pT, U1b_h, U1b_l,
                                                   ub1, U2_h, U2_l, ub2,
                                                   ln_g + (size_t)l * HID,
                                                   ln_b + (size_t)l * HID, px, N);
    }

    cudaMemsetAsync(pcs, 0, HID * sizeof(float));
    colsum_kernel<<<128, 256>>>(px, pcs, N);
    head_kernel<<<1, HID>>>(pcs, out_W1, out_b1, out_W2, out_b2,
                            (float*)d_out, 1.0f / (float)N);
}